// round 12
// baseline (speedup 1.0000x reference)
#include <cuda_runtime.h>
#include <math.h>

#define NNODES 512
#define IND    768
#define HIDD   64
#define NHEAD  4
#define HD1    256
#define KCC    192
#define OUTDIM 256
#define NT     768
#define NG     3
#define GSZ    256
#define SMG    5184         // smem floats per warpgroup
#define RS     20           // smem row stride (16 k + 4 pad)
#define JOBSLOT 5120        // per-group smem job ticket slot

// ----------------------------------------------------------------------------
// Device scratch
// ----------------------------------------------------------------------------
__device__ float g_z1[NNODES * HD1];
__device__ float g_h1[NNODES * HD1];
__device__ float g_z2[NNODES * IND];
__device__ float g_h2[NNODES * IND];
__device__ float g_r [NNODES * KCC];
__device__ float g_part[4 * NNODES * IND];
__device__ float g_ssrc[NHEAD * NNODES], g_sdst[NHEAD * NNODES];
__device__ float g_Af[NHEAD * NNODES], g_Cf[NHEAD * NNODES];
__device__ float g_Bp[NHEAD * NNODES], g_Dp[NHEAD * NNODES];
__device__ float g_sumexp[IND];
__device__ float g_rsum[KCC];
__device__ unsigned g_tick[8];
__device__ unsigned g_cnt8[8];
__device__ unsigned g_root = 0;
__device__ volatile unsigned g_bargen = 0;

// ----------------------------------------------------------------------------
// Barriers + cp.async helpers
// ----------------------------------------------------------------------------
__device__ __forceinline__ void wgsync(int wg) {
    asm volatile("bar.sync %0, %1;" :: "r"(wg + 1), "n"(GSZ) : "memory");
}

__device__ __forceinline__ void gridbar() {
    __syncthreads();
    if (threadIdx.x == 0) {
        __threadfence();
        const unsigned gen = g_bargen;
        const unsigned b = blockIdx.x & 7u;
        const unsigned bsz = (gridDim.x >> 3) + (((gridDim.x & 7u) > b) ? 1u : 0u);
        if (atomicAdd(&g_cnt8[b], 1u) == bsz - 1u) {
            atomicExch(&g_cnt8[b], 0u);
            __threadfence();
            if (atomicAdd(&g_root, 1u) == 7u) {
                atomicExch(&g_root, 0u);
                __threadfence();
                atomicAdd((unsigned*)&g_bargen, 1u);
            }
        }
        while (g_bargen == gen) { __nanosleep(16); }
        __threadfence();
    }
    __syncthreads();
}

__device__ __forceinline__ unsigned su32(const void* p) {
    return (unsigned)__cvta_generic_to_shared(p);
}
__device__ __forceinline__ void cpa16(unsigned d, const void* s) {
    asm volatile("cp.async.cg.shared.global [%0], [%1], 16;" :: "r"(d), "l"(s));
}
__device__ __forceinline__ void cpcommit() { asm volatile("cp.async.commit_group;"); }
__device__ __forceinline__ void cpwait0()  { asm volatile("cp.async.wait_group 0;"); }

// steal one job for the warpgroup; returns -1 when exhausted
__device__ __forceinline__ int steal(unsigned* tick, int njobs, int ltid, int wg,
                                     float* gsm)
{
    volatile unsigned* slot = (volatile unsigned*)(gsm + JOBSLOT);
    if (ltid == 0) *slot = atomicAdd(tick, 1u);
    wgsync(wg);
    int job = (int)*slot;
    return (job < njobs) ? job : -1;
}

// ----------------------------------------------------------------------------
// Pipelined SGEMM 64x64, 4x4/thread, chunk=16, one barrier/chunk, stealing.
// ----------------------------------------------------------------------------
__device__ void ph_gemm_abt(const float* __restrict__ A, const float* __restrict__ B,
                            float* __restrict__ C, int Ncols, int K_ld, int klen,
                            int gx, int gy, int nsplit, unsigned* tick,
                            int ltid, int wg, float* gsm)
{
    float* As = gsm;                 // 2 * 1280
    float* Bs = gsm + 2560;          // 2 * 1280
    const int tx = ltid & 15, ty = ltid >> 4;
    const int isB  = ltid >> 7;
    const int lrow = (ltid & 127) >> 1;
    const int lh   = ltid & 1;
    const int njobs = gx * gy * nsplit;
    const int nch = klen >> 4;

    for (;;) {
        const int job = steal(tick, njobs, ltid, wg, gsm);   // wgsync inside
        if (job < 0) break;
        const int z = job / (gx * gy);
        const int rem = job % (gx * gy);
        const int by = rem / gx, bx = rem % gx;
        const int m0 = by * 64, n0 = bx * 64, kstart = z * klen;

        const float* src0 = isB ? (B + (size_t)(n0 + lrow) * K_ld + kstart + lh * 8)
                                : (A + (size_t)(m0 + lrow) * K_ld + kstart + lh * 8);
        const unsigned dst0 = isB ? su32(&Bs[lrow * RS + lh * 8])
                                  : su32(&As[lrow * RS + lh * 8]);

        float acc[4][4];
#pragma unroll
        for (int i = 0; i < 4; i++)
#pragma unroll
            for (int j = 0; j < 4; j++) acc[i][j] = 0.f;

        cpa16(dst0, src0);
        cpa16(dst0 + 16, src0 + 4);
        cpcommit();

        for (int c = 0; c < nch; c++) {
            const int cb = c & 1;
            cpwait0();
            wgsync(wg);
            if (c + 1 < nch) {
                const unsigned d = dst0 + (cb ^ 1) * 5120;
                const float* s = src0 + (c + 1) * 16;
                cpa16(d, s);
                cpa16(d + 16, s + 4);
                cpcommit();
            }
            const float* Ab = As + cb * 1280;
            const float* Bb = Bs + cb * 1280;
#pragma unroll
            for (int q = 0; q < 4; q++) {
                float4 af[4], bf[4];
#pragma unroll
                for (int i = 0; i < 4; i++)
                    af[i] = *(const float4*)&Ab[(ty + 16 * i) * RS + q * 4];
#pragma unroll
                for (int j = 0; j < 4; j++)
                    bf[j] = *(const float4*)&Bb[(tx + 16 * j) * RS + q * 4];
#pragma unroll
                for (int i = 0; i < 4; i++)
#pragma unroll
                    for (int j = 0; j < 4; j++) {
                        acc[i][j] += af[i].x * bf[j].x;
                        acc[i][j] += af[i].y * bf[j].y;
                        acc[i][j] += af[i].z * bf[j].z;
                        acc[i][j] += af[i].w * bf[j].w;
                    }
            }
        }
        wgsync(wg);     // all done with smem before next steal overwrites

        float* outp = C + (size_t)z * NNODES * Ncols;
#pragma unroll
        for (int i = 0; i < 4; i++)
#pragma unroll
            for (int j = 0; j < 4; j++)
                outp[(size_t)(m0 + ty + 16 * i) * Ncols + n0 + tx + 16 * j] = acc[i][j];
    }
}

// ----------------------------------------------------------------------------
// Pipelined aggregation GEMM 64x64, stealing. alpha built on the fly.
// ----------------------------------------------------------------------------
__device__ void ph_gemm_agg(const float* __restrict__ Z, float* __restrict__ C,
                            const float* __restrict__ ssrc, const float* __restrict__ sdst,
                            const float* __restrict__ Af, const float* __restrict__ Cf,
                            const float* __restrict__ Bp, const float* __restrict__ Dp,
                            int ldz, int hd, int gx, int gy, int nsplit, int H,
                            int klen, int ldc, unsigned* tick,
                            int ltid, int wg, float* gsm)
{
    float* Asb = gsm;              // 2 * 1088
    float* Zs  = gsm + 2176;       // 2 * 1088
    float* Ex  = gsm + 4352;       // 192
    const int tx = ltid & 15, ty = ltid >> 4;
    const int zrow = ltid >> 4, zf4 = ltid & 15;
    const int ail = ltid >> 4, aj4 = (ltid & 15) * 4;
    const int jobs_per_h = gx * gy * nsplit;
    const int njobs = H * jobs_per_h;
    const int nch = klen >> 4;

    for (;;) {
        const int job = steal(tick, njobs, ltid, wg, gsm);
        if (job < 0) break;
        const int h = job / jobs_per_h;
        int rem = job % jobs_per_h;
        const int z = rem / (gx * gy); rem %= gx * gy;
        const int by = rem / gx, bx = rem % gx;
        const int m0 = by * 64, ncol0 = h * hd + bx * 64, kstart = z * klen;
        const float* ss = ssrc + h * NNODES;
        const float* af = Af + h * NNODES;
        const float* cf = Cf + h * NNODES;

        auto build = [&](int cc, float* dst) {
            int ig = kstart + cc * 16 + ail;
            float ssv = ss[ig], afv = af[ig], cfv = cf[ig];
            int jj = aj4;
            float4 w;
            float x0 = ssv + Ex[jj + 0];
            float x1 = ssv + Ex[jj + 1];
            float x2 = ssv + Ex[jj + 2];
            float x3 = ssv + Ex[jj + 3];
            w.x = x0 > 0.f ? afv * Ex[64 + jj + 0] : cfv * Ex[128 + jj + 0];
            w.y = x1 > 0.f ? afv * Ex[64 + jj + 1] : cfv * Ex[128 + jj + 1];
            w.z = x2 > 0.f ? afv * Ex[64 + jj + 2] : cfv * Ex[128 + jj + 2];
            w.w = x3 > 0.f ? afv * Ex[64 + jj + 3] : cfv * Ex[128 + jj + 3];
            if (ig == m0 + jj + 0) w.x = 0.f;
            if (ig == m0 + jj + 1) w.y = 0.f;
            if (ig == m0 + jj + 2) w.z = 0.f;
            if (ig == m0 + jj + 3) w.w = 0.f;
            *(float4*)&dst[ail * 68 + aj4] = w;
        };

        if (ltid < 64) {
            int j = m0 + ltid;
            Ex[ltid]       = sdst[h * NNODES + j];
            Ex[64 + ltid]  = Bp[h * NNODES + j];
            Ex[128 + ltid] = Dp[h * NNODES + j];
        }
        wgsync(wg);                         // Ex visible to ALL threads

        build(0, Asb);
        const float* srcZ = Z + (size_t)(kstart + zrow) * ldz + ncol0 + zf4 * 4;
        const unsigned dstZ = su32(&Zs[zrow * 68 + zf4 * 4]);
        cpa16(dstZ, srcZ);
        cpcommit();

        float acc[4][4];
#pragma unroll
        for (int i = 0; i < 4; i++)
#pragma unroll
            for (int j = 0; j < 4; j++) acc[i][j] = 0.f;

        for (int c = 0; c < nch; c++) {
            const int cb = c & 1;
            cpwait0();
            wgsync(wg);
            if (c + 1 < nch) {
                cpa16(dstZ + (cb ^ 1) * 4352, srcZ + (size_t)(c + 1) * 16 * ldz);
                cpcommit();
                build(c + 1, Asb + (cb ^ 1) * 1088);
            }
            const float* Ab = Asb + cb * 1088;
            const float* Zb = Zs  + cb * 1088;
#pragma unroll
            for (int kk = 0; kk < 16; kk++) {
                float4 a = *(const float4*)&Ab[kk * 68 + ty * 4];
                float4 b = *(const float4*)&Zb[kk * 68 + tx * 4];
                float a4[4] = {a.x, a.y, a.z, a.w};
                float b4[4] = {b.x, b.y, b.z, b.w};
#pragma unroll
                for (int i = 0; i < 4; i++)
#pragma unroll
                    for (int j = 0; j < 4; j++) acc[i][j] += a4[i] * b4[j];
            }
        }
        wgsync(wg);

        float* outp = C + (size_t)z * NNODES * ldc;
#pragma unroll
        for (int i = 0; i < 4; i++)
#pragma unroll
            for (int j = 0; j < 4; j++)
                outp[(size_t)(m0 + ty * 4 + i) * ldc + ncol0 + tx * 4 + j] = acc[i][j];
    }
}

// ----------------------------------------------------------------------------
// fc1 GEMM with softmax folded into A build: A = exp(h2) / sumexp[col].
// (max subtraction dropped — softmax is shift-invariant and |h2| is small)
// ----------------------------------------------------------------------------
__device__ void ph_gemm_fc1(const float* __restrict__ h2m,
                            const float* __restrict__ sumexp,
                            const float* __restrict__ Bw,
                            float* __restrict__ C, unsigned* tick,
                            int ltid, int wg, float* gsm)
{
    float* As = gsm;
    float* Bs = gsm + 2560;
    const int tx = ltid & 15, ty = ltid >> 4;
    const int row = ltid >> 2, kq = (ltid & 3) * 4;
    const int njobs = 384;
    const int nch = 3;

    for (;;) {
        const int job = steal(tick, njobs, ltid, wg, gsm);
        if (job < 0) break;
        const int z = job / 24;
        const int rem = job % 24;
        const int by = rem / 3, bx = rem % 3;
        const int m0 = by * 64, n0 = bx * 64, kstart = z * 48;

        const unsigned dstB = su32(&Bs[row * RS + kq]);
        const float* srcB = Bw + (size_t)(n0 + row) * IND + kstart + kq;
        const float* srcA = h2m + (size_t)(m0 + row) * IND + kstart + kq;

        float acc[4][4];
#pragma unroll
        for (int i = 0; i < 4; i++)
#pragma unroll
            for (int j = 0; j < 4; j++) acc[i][j] = 0.f;

        cpa16(dstB, srcB);
        cpcommit();
        {
            float4 raw = *(const float4*)srcA;
            float4 se  = *(const float4*)&sumexp[kstart + kq];
            float4 v;
            v.x = __expf(raw.x) / se.x;
            v.y = __expf(raw.y) / se.y;
            v.z = __expf(raw.z) / se.z;
            v.w = __expf(raw.w) / se.w;
            *(float4*)&As[row * RS + kq] = v;
        }

        for (int c = 0; c < nch; c++) {
            const int cb = c & 1;
            cpwait0();
            wgsync(wg);
            float4 raw;
            const bool pre = (c + 1 < nch);
            if (pre) {
                cpa16(dstB + (cb ^ 1) * 5120u, srcB + (c + 1) * 16);
                cpcommit();
                raw = *(const float4*)(srcA + (c + 1) * 16);
            }
            const float* Ab = As + cb * 1280;
            const float* Bb = Bs + cb * 1280;
#pragma unroll
            for (int q = 0; q < 4; q++) {
                float4 af[4], bf[4];
#pragma unroll
                for (int i = 0; i < 4; i++)
                    af[i] = *(const float4*)&Ab[(ty + 16 * i) * RS + q * 4];
#pragma unroll
                for (int j = 0; j < 4; j++)
                    bf[j] = *(const float4*)&Bb[(tx + 16 * j) * RS + q * 4];
#pragma unroll
                for (int i = 0; i < 4; i++)
#pragma unroll
                    for (int j = 0; j < 4; j++) {
                        acc[i][j] += af[i].x * bf[j].x;
                        acc[i][j] += af[i].y * bf[j].y;
                        acc[i][j] += af[i].z * bf[j].z;
                        acc[i][j] += af[i].w * bf[j].w;
                    }
            }
            if (pre) {
                const int kg = kstart + (c + 1) * 16 + kq;
                float4 se = *(const float4*)&sumexp[kg];
                float4 v;
                v.x = __expf(raw.x) / se.x;
                v.y = __expf(raw.y) / se.y;
                v.z = __expf(raw.z) / se.z;
                v.w = __expf(raw.w) / se.w;
                *(float4*)&As[(cb ^ 1) * 1280 + row * RS + kq] = v;
            }
        }
        wgsync(wg);

        float* outp = C + (size_t)z * NNODES * KCC;
#pragma unroll
        for (int i = 0; i < 4; i++)
#pragma unroll
            for (int j = 0; j < 4; j++)
                outp[(size_t)(m0 + ty + 16 * i) * KCC + n0 + tx + 16 * j] = acc[i][j];
    }
}

// ----------------------------------------------------------------------------
// Fused combine + layer1 scores. Block (768 thr) = 3 rows of z1 per iteration.
// ----------------------------------------------------------------------------
__device__ void ph_combine_scores1(const float* __restrict__ part, int nparts,
                                   const float* __restrict__ a1,
                                   float* __restrict__ z1,
                                   float* __restrict__ ssrc, float* __restrict__ sdst,
                                   float* smblk)
{
    const int tid = threadIdx.x;
    const int total = NNODES * HD1;
    const int d = tid & 255, h = d >> 6, l = d & 63;
    const float a_s = a1[h * 128 + l];
    const float a_d = a1[h * 128 + 64 + l];

    for (int base = blockIdx.x * NT; base < total; base += gridDim.x * NT) {
        const int idx = base + tid;
        float v = 0.f;
        if (idx < total) {
            for (int p = 0; p < nparts; p++) v += part[(size_t)p * total + idx];
            z1[idx] = v;
        }
        float s1 = v * a_s, s2 = v * a_d;
#pragma unroll
        for (int o = 16; o; o >>= 1) {
            s1 += __shfl_xor_sync(0xffffffffu, s1, o);
            s2 += __shfl_xor_sync(0xffffffffu, s2, o);
        }
        const int w = tid >> 5;
        if ((tid & 31) == 0) { smblk[w] = s1; smblk[24 + w] = s2; }
        __syncthreads();
        if (tid < 12) {
            float t1 = smblk[2 * tid] + smblk[2 * tid + 1];
            float t2 = smblk[24 + 2 * tid] + smblk[24 + 2 * tid + 1];
            int row = (base >> 8) + (tid >> 2);
            int hh = tid & 3;
            if (row < NNODES) {
                ssrc[hh * NNODES + row] = t1;
                sdst[hh * NNODES + row] = t2;
            }
        }
        __syncthreads();
    }
}

// ----------------------------------------------------------------------------
// Fused combine + layer2 scores. Block = exactly 1 row of z2 per iteration.
// ----------------------------------------------------------------------------
__device__ void ph_combine_scores2(const float* __restrict__ part, int nparts,
                                   const float* __restrict__ a2,
                                   float* __restrict__ z2,
                                   float* __restrict__ ssrc, float* __restrict__ sdst,
                                   float* smblk)
{
    const int tid = threadIdx.x;
    const int total = NNODES * IND;
    const float a_s = a2[tid];
    const float a_d = a2[IND + tid];

    for (int base = blockIdx.x * NT; base < total; base += gridDim.x * NT) {
        const int idx = base + tid;
        float v = 0.f;
        for (int p = 0; p < nparts; p++) v += part[(size_t)p * total + idx];
        z2[idx] = v;
        float s1 = v * a_s, s2 = v * a_d;
#pragma unroll
        for (int o = 16; o; o >>= 1) {
            s1 += __shfl_xor_sync(0xffffffffu, s1, o);
            s2 += __shfl_xor_sync(0xffffffffu, s2, o);
        }
        const int w = tid >> 5;
        if ((tid & 31) == 0) { smblk[w] = s1; smblk[24 + w] = s2; }
        __syncthreads();
        if (tid == 0) {
            float t1 = 0.f, t2 = 0.f;
            for (int q = 0; q < 24; q++) { t1 += smblk[q]; t2 += smblk[24 + q]; }
            const int row = base / IND;
            ssrc[row] = t1;
            sdst[row] = t2;
        }
        __syncthreads();
    }
}

// ----------------------------------------------------------------------------
// Fused h2 combine + column exp-sum (atomic; no max needed).
// Vectorized float4; each thread owns fixed columns.
// ----------------------------------------------------------------------------
__device__ void ph_combine_h2_sumexp(const float* __restrict__ part, int nparts,
                                     float* __restrict__ h2)
{
    const int total4 = NNODES * IND / 4;
    const float4* part4 = (const float4*)part;
    for (int q = blockIdx.x * NT + threadIdx.x; q < total4; q += gridDim.x * NT) {
        float4 s = make_float4(0.f, 0.f, 0.f, 0.f);
        for (int p = 0; p < nparts; p++) {
            float4 v = part4[(size_t)p * total4 + q];
            s.x += v.x; s.y += v.y; s.z += v.z; s.w += v.w;
        }
        *(float4*)&h2[q * 4] = s;
        const int c = (q * 4) % IND;
        atomicAdd(&g_sumexp[c + 0], __expf(s.x));
        atomicAdd(&g_sumexp[c + 1], __expf(s.y));
        atomicAdd(&g_sumexp[c + 2], __expf(s.z));
        atomicAdd(&g_sumexp[c + 3], __expf(s.w));
    }
}

// ----------------------------------------------------------------------------
// Fused fc1 combine + bias + relu + column-sum (atomic). Block = 4 rows of r.
// ----------------------------------------------------------------------------
__device__ void ph_combine_relu_colsum(const float* __restrict__ part, int nparts,
                                       const float* __restrict__ bias,
                                       float* __restrict__ r, float* smblk)
{
    const int tid = threadIdx.x;
    const int total = NNODES * KCC;
    const float b = bias[tid % KCC];

    for (int base = blockIdx.x * NT; base < total; base += gridDim.x * NT) {
        const int idx = base + tid;
        float v = 0.f;
        for (int p = 0; p < nparts; p++) v += part[(size_t)p * total + idx];
        v = fmaxf(v + b, 0.f);
        r[idx] = v;
        smblk[tid] = v;
        __syncthreads();
        if (tid < KCC)
            atomicAdd(&g_rsum[tid],
                      smblk[tid] + smblk[tid + KCC] + smblk[tid + 2 * KCC] +
                      smblk[tid + 3 * KCC]);
        __syncthreads();
    }
}

// ----------------------------------------------------------------------------
// Plain combine (ELU / none), vectorized float4
// ----------------------------------------------------------------------------
__device__ void ph_combine(float* __restrict__ out, const float* __restrict__ part,
                           int nparts, int total, int act)
{
    const int total4 = total / 4;
    const float4* part4 = (const float4*)part;
    for (int q = blockIdx.x * NT + threadIdx.x; q < total4; q += gridDim.x * NT) {
        float4 s = make_float4(0.f, 0.f, 0.f, 0.f);
        for (int p = 0; p < nparts; p++) {
            float4 v = part4[(size_t)p * total4 + q];
            s.x += v.x; s.y += v.y; s.z += v.z; s.w += v.w;
        }
        if (act == 2) {
            s.x = s.x > 0.f ? s.x : expm1f(s.x);
            s.y = s.y > 0.f ? s.y : expm1f(s.y);
            s.z = s.z > 0.f ? s.z : expm1f(s.z);
            s.w = s.w > 0.f ? s.w : expm1f(s.w);
        }
        *(float4*)&out[q * 4] = s;
    }
}

// ----------------------------------------------------------------------------
// Separable-softmax stats (static mapping; 32 / 8 jobs)
// ----------------------------------------------------------------------------
__device__ void ph_stats(const float* __restrict__ ssrc, const float* __restrict__ sdst,
                         float* __restrict__ Af, float* __restrict__ Cf,
                         float* __restrict__ Bpg, float* __restrict__ Dpg,
                         int H, int ltid, int wg, int grp, int ngrp, float* gsm)
{
    float* ss  = gsm;
    float* aa  = gsm + 512;
    float* cc  = gsm + 1024;
    float* rm1 = gsm + 1536;
    float* rm2 = gsm + 1792;
    int*   ri1 = (int*)(gsm + 2048);
    const int cpj = NNODES / 64;
    const int njobs = H * cpj;

    for (int job = grp; job < njobs; job += ngrp) {
        const int h = job / cpj, jc = job % cpj;
        wgsync(wg);
        for (int i = ltid; i < NNODES; i += GSZ) ss[i] = ssrc[h * NNODES + i];
        wgsync(wg);

        float m1 = -1e30f, m2 = -1e30f; int i1 = -1;
        for (int i = ltid; i < NNODES; i += GSZ) {
            float v = ss[i];
            if (v > m1) { m2 = m1; m1 = v; i1 = i; }
            else if (v > m2) m2 = v;
        }
        rm1[ltid] = m1; rm2[ltid] = m2; ri1[ltid] = i1;
        wgsync(wg);
        if (ltid < 32) {
            float a1 = rm1[ltid], a2 = rm2[ltid]; int ai = ri1[ltid];
            for (int t = ltid + 32; t < GSZ; t += 32) {
                float b1 = rm1[t], b2 = rm2[t];
                if (b1 > a1) { a2 = fmaxf(a1, b2); a1 = b1; ai = ri1[t]; }
                else         { a2 = fmaxf(a2, b1); }
            }
            rm1[ltid] = a1; rm2[ltid] = a2; ri1[ltid] = ai;
        }
        wgsync(wg);
        if (ltid == 0) {
            float a1 = rm1[0], a2 = rm2[0]; int ai = ri1[0];
            for (int t = 1; t < 32; t++) {
                float b1 = rm1[t], b2 = rm2[t];
                if (b1 > a1) { a2 = fmaxf(a1, b2); a1 = b1; ai = ri1[t]; }
                else         { a2 = fmaxf(a2, b1); }
            }
            rm1[0] = a1; rm2[0] = a2; ri1[0] = ai;
        }
        wgsync(wg);
        const float Ms = rm1[0], M2 = rm2[0];
        const int iarg = ri1[0];

        for (int i = ltid; i < NNODES; i += GSZ) {
            float dd = ss[i] - Ms;
            aa[i] = __expf(dd);
            cc[i] = __expf(0.01f * dd);
        }
        wgsync(wg);
        if (jc == 0) {
            for (int i = ltid; i < NNODES; i += GSZ) {
                Af[h * NNODES + i] = aa[i];
                Cf[h * NNODES + i] = cc[i];
            }
        }

        const int wid = ltid >> 5, lane = ltid & 31;
        for (int jj = wid; jj < 64; jj += 8) {
            int j = jc * 64 + jj;
            float sd = sdst[h * NNODES + j];
            float smx = (j == iarg) ? M2 : Ms;
            float t0 = smx + sd;
            float mxj = t0 > 0.f ? t0 : 0.01f * t0;
            float Bj = __expf(Ms + sd - mxj);
            float Dj = __expf(0.01f * (Ms + sd) - mxj);
            float ssum = 0.f;
            for (int i = lane; i < NNODES; i += 32) {
                if (i == j) continue;
                float x = ss[i] + sd;
                ssum += (x > 0.f) ? aa[i] * Bj : cc[i] * Dj;
            }
#pragma unroll
            for (int o = 16; o; o >>= 1) ssum += __shfl_xor_sync(0xffffffffu, ssum, o);
            if (lane == 0) {
                float inv = 1.f / ssum;
                Bpg[h * NNODES + j] = Bj * inv;
                Dpg[h * NNODES + j] = Dj * inv;
            }
        }
    }
}

// ----------------------------------------------------------------------------
// fc2: warp per output
// ----------------------------------------------------------------------------
__device__ void ph_fc2(const float* __restrict__ rsum, const float* __restrict__ w,
                       const float* __restrict__ b, float* __restrict__ out)
{
    const int lane = threadIdx.x & 31;
    const int gw = blockIdx.x * (NT / 32) + (threadIdx.x >> 5);
    const int nw = gridDim.x * (NT / 32);
    for (int o = gw; o < OUTDIM; o += nw) {
        float s = 0.f;
        for (int k = lane; k < KCC; k += 32) s += rsum[k] * w[(size_t)o * KCC + k];
#pragma unroll
        for (int of = 16; of; of >>= 1) s += __shfl_xor_sync(0xffffffffu, s, of);
        if (lane == 0) out[o] = (float)NNODES * b[o] + s;
    }
}

// ----------------------------------------------------------------------------
// Persistent mega-kernel
// ----------------------------------------------------------------------------
__global__ void __launch_bounds__(NT, 1)
gat_mega(const float* __restrict__ X,  const float* __restrict__ W1,
         const float* __restrict__ a1, const float* __restrict__ W2,
         const float* __restrict__ a2, const float* __restrict__ fc1w,
         const float* __restrict__ fc1b, const float* __restrict__ fc2w,
         const float* __restrict__ fc2b, float* __restrict__ out)
{
    extern __shared__ float sm[];
    const int wg = threadIdx.x >> 8;
    const int ltid = threadIdx.x & 255;
    float* gsm = sm + wg * SMG;
    const int grp = wg * gridDim.x + blockIdx.x;
    const int ngrp = gridDim.x * NG;

    // INIT: reset tickets, rsum, sumexp
    if (blockIdx.x == 0) {
        if (threadIdx.x < 8) g_tick[threadIdx.x] = 0;
        if (threadIdx.x >= 32 && threadIdx.x < 32 + KCC) g_rsum[threadIdx.x - 32] = 0.f;
    }
    if (blockIdx.x == 1 && threadIdx.x < IND) g_sumexp[threadIdx.x] = 0.f;
    gridbar();
    // P0: z1 partials = X @ W1^T, split 12 (384 jobs)
    ph_gemm_abt(X, W1, g_part, HD1, IND, 64, HD1 / 64, NNODES / 64, 12,
                &g_tick[0], ltid, wg, gsm);
    gridbar();
    // P1: combine -> z1 + layer1 scores (fused)
    ph_combine_scores1(g_part, 12, a1, g_z1, g_ssrc, g_sdst, sm);
    gridbar();
    // P2: layer1 stats
    ph_stats(g_ssrc, g_sdst, g_Af, g_Cf, g_Bp, g_Dp, NHEAD, ltid, wg, grp, ngrp, gsm);
    gridbar();
    // P3: agg1 partials, split 8 (256 jobs)
    ph_gemm_agg(g_z1, g_part, g_ssrc, g_sdst, g_Af, g_Cf, g_Bp, g_Dp,
                HD1, HIDD, 1, NNODES / 64, 8, NHEAD, 64, HD1,
                &g_tick[1], ltid, wg, gsm);
    gridbar();
    // P4: combine + ELU -> h1
    ph_combine(g_h1, g_part, 8, NNODES * HD1, 2);
    gridbar();
    // P5: z2 partials = h1 @ W2^T, split 4 (384 jobs)
    ph_gemm_abt(g_h1, W2, g_part, IND, HD1, 64, IND / 64, NNODES / 64, 4,
                &g_tick[2], ltid, wg, gsm);
    gridbar();
    // P6: combine -> z2 + layer2 scores (fused)
    ph_combine_scores2(g_part, 4, a2, g_z2, g_ssrc, g_sdst, sm);
    gridbar();
    // P7: layer2 stats
    ph_stats(g_ssrc, g_sdst, g_Af, g_Cf, g_Bp, g_Dp, 1, ltid, wg, grp, ngrp, gsm);
    gridbar();
    // P8: agg2 partials, split 4 (384 jobs, klen 128)
    ph_gemm_agg(g_z2, g_part, g_ssrc, g_sdst, g_Af, g_Cf, g_Bp, g_Dp,
                IND, 0, IND / 64, NNODES / 64, 4, 1, 128, IND,
                &g_tick[3], ltid, wg, gsm);
    gridbar();
    // P9: combine -> h2 + column exp-sums (fused; no max pass)
    ph_combine_h2_sumexp(g_part, 4, g_h2);
    gridbar();
    // P10: fc1 partials = softmax(h2) @ fc1_w^T (exp/denominator fused), 384 jobs
    ph_gemm_fc1(g_h2, g_sumexp, fc1w, g_part, &g_tick[4], ltid, wg, gsm);
    gridbar();
    // P11: combine + bias + relu -> r, + atomic column sum (fused)
    ph_combine_relu_colsum(g_part, 16, fc1b, g_r, sm);
    gridbar();
    // P12: fc2 -> out
    ph_fc2(g_rsum, fc2w, fc2b, out);
}

// ----------------------------------------------------------------------------
// Launch
// ----------------------------------------------------------------------------
extern "C" void kernel_launch(void* const* d_in, const int* in_sizes, int n_in,
                              void* d_out, int out_size)
{
    const float* X     = (const float*)d_in[0];
    const float* W1    = (const float*)d_in[1];
    const float* a1    = (const float*)d_in[2];
    const float* W2    = (const float*)d_in[3];
    const float* a2    = (const float*)d_in[4];
    const float* fc1_w = (const float*)d_in[5];
    const float* fc1_b = (const float*)d_in[6];
    const float* fc2_w = (const float*)d_in[7];
    const float* fc2_b = (const float*)d_in[8];

    int sms = 148;
    cudaDeviceGetAttribute(&sms, cudaDevAttrMultiProcessorCount, 0);

    const size_t smbytes = (size_t)NG * SMG * sizeof(float);   // ~61 KB
    cudaFuncSetAttribute(gat_mega, cudaFuncAttributeMaxDynamicSharedMemorySize,
                         (int)smbytes);

    gat_mega<<<sms, NT, smbytes>>>(X, W1, a1, W2, a2, fc1_w, fc1_b, fc2_w, fc2_b,
                                   (float*)d_out);
}

// round 13
// speedup vs baseline: 1.0727x; 1.0727x over previous
#include <cuda_runtime.h>
#include <math.h>

#define NNODES 512
#define IND    768
#define HIDD   64
#define NHEAD  4
#define HD1    256
#define KCC    192
#define OUTDIM 256
#define NT     768
#define NG     3
#define GSZ    256
#define SMG    5184         // smem floats per warpgroup
#define RS     20           // smem row stride (16 k + 4 pad)
#define JOBSLOT 5120        // per-group smem job ticket slot

// ----------------------------------------------------------------------------
// Device scratch
// ----------------------------------------------------------------------------
__device__ float g_z1[NNODES * HD1];
__device__ float g_h1[NNODES * HD1];
__device__ float g_z2[NNODES * IND];
__device__ float g_h2[NNODES * IND];
__device__ float g_r [NNODES * KCC];
__device__ float g_part[4 * NNODES * IND];
__device__ float g_ssrc[NHEAD * NNODES], g_sdst[NHEAD * NNODES];
__device__ float g_Af[NHEAD * NNODES], g_Cf[NHEAD * NNODES];
__device__ float g_Bp[NHEAD * NNODES], g_Dp[NHEAD * NNODES];
__device__ float g_mxc[IND], g_invc[IND];
__device__ float g_rsum[KCC];
__device__ unsigned g_tick[8];
__device__ unsigned g_cnt8[8];
__device__ unsigned g_root = 0;
__device__ volatile unsigned g_bargen = 0;

// ----------------------------------------------------------------------------
// Barriers + cp.async helpers
// ----------------------------------------------------------------------------
__device__ __forceinline__ void wgsync(int wg) {
    asm volatile("bar.sync %0, %1;" :: "r"(wg + 1), "n"(GSZ) : "memory");
}

__device__ __forceinline__ void gridbar() {
    __syncthreads();
    if (threadIdx.x == 0) {
        __threadfence();
        const unsigned gen = g_bargen;
        const unsigned b = blockIdx.x & 7u;
        const unsigned bsz = (gridDim.x >> 3) + (((gridDim.x & 7u) > b) ? 1u : 0u);
        if (atomicAdd(&g_cnt8[b], 1u) == bsz - 1u) {
            atomicExch(&g_cnt8[b], 0u);
            __threadfence();
            if (atomicAdd(&g_root, 1u) == 7u) {
                atomicExch(&g_root, 0u);
                __threadfence();
                atomicAdd((unsigned*)&g_bargen, 1u);
            }
        }
        while (g_bargen == gen) { __nanosleep(32); }
        __threadfence();
    }
    __syncthreads();
}

__device__ __forceinline__ unsigned su32(const void* p) {
    return (unsigned)__cvta_generic_to_shared(p);
}
__device__ __forceinline__ void cpa16(unsigned d, const void* s) {
    asm volatile("cp.async.cg.shared.global [%0], [%1], 16;" :: "r"(d), "l"(s));
}
__device__ __forceinline__ void cpcommit() { asm volatile("cp.async.commit_group;"); }
__device__ __forceinline__ void cpwait0()  { asm volatile("cp.async.wait_group 0;"); }

// steal one job for the warpgroup; returns -1 when exhausted
__device__ __forceinline__ int steal(unsigned* tick, int njobs, int ltid, int wg,
                                     float* gsm)
{
    volatile unsigned* slot = (volatile unsigned*)(gsm + JOBSLOT);
    if (ltid == 0) *slot = atomicAdd(tick, 1u);
    wgsync(wg);
    int job = (int)*slot;
    return (job < njobs) ? job : -1;
}

// ----------------------------------------------------------------------------
// Pipelined SGEMM 64x64, 4x4/thread, chunk=16, one barrier/chunk, stealing.
// ----------------------------------------------------------------------------
__device__ void ph_gemm_abt(const float* __restrict__ A, const float* __restrict__ B,
                            float* __restrict__ C, int Ncols, int K_ld, int klen,
                            int gx, int gy, int nsplit, unsigned* tick,
                            int ltid, int wg, float* gsm)
{
    float* As = gsm;                 // 2 * 1280
    float* Bs = gsm + 2560;          // 2 * 1280
    const int tx = ltid & 15, ty = ltid >> 4;
    const int isB  = ltid >> 7;
    const int lrow = (ltid & 127) >> 1;
    const int lh   = ltid & 1;
    const int njobs = gx * gy * nsplit;
    const int nch = klen >> 4;

    for (;;) {
        const int job = steal(tick, njobs, ltid, wg, gsm);   // wgsync inside
        if (job < 0) break;
        const int z = job / (gx * gy);
        const int rem = job % (gx * gy);
        const int by = rem / gx, bx = rem % gx;
        const int m0 = by * 64, n0 = bx * 64, kstart = z * klen;

        const float* src0 = isB ? (B + (size_t)(n0 + lrow) * K_ld + kstart + lh * 8)
                                : (A + (size_t)(m0 + lrow) * K_ld + kstart + lh * 8);
        const unsigned dst0 = isB ? su32(&Bs[lrow * RS + lh * 8])
                                  : su32(&As[lrow * RS + lh * 8]);

        float acc[4][4];
#pragma unroll
        for (int i = 0; i < 4; i++)
#pragma unroll
            for (int j = 0; j < 4; j++) acc[i][j] = 0.f;

        cpa16(dst0, src0);
        cpa16(dst0 + 16, src0 + 4);
        cpcommit();

        for (int c = 0; c < nch; c++) {
            const int cb = c & 1;
            cpwait0();
            wgsync(wg);
            if (c + 1 < nch) {
                const unsigned d = dst0 + (cb ^ 1) * 5120;
                const float* s = src0 + (c + 1) * 16;
                cpa16(d, s);
                cpa16(d + 16, s + 4);
                cpcommit();
            }
            const float* Ab = As + cb * 1280;
            const float* Bb = Bs + cb * 1280;
#pragma unroll
            for (int q = 0; q < 4; q++) {
                float4 af[4], bf[4];
#pragma unroll
                for (int i = 0; i < 4; i++)
                    af[i] = *(const float4*)&Ab[(ty + 16 * i) * RS + q * 4];
#pragma unroll
                for (int j = 0; j < 4; j++)
                    bf[j] = *(const float4*)&Bb[(tx + 16 * j) * RS + q * 4];
#pragma unroll
                for (int i = 0; i < 4; i++)
#pragma unroll
                    for (int j = 0; j < 4; j++) {
                        acc[i][j] += af[i].x * bf[j].x;
                        acc[i][j] += af[i].y * bf[j].y;
                        acc[i][j] += af[i].z * bf[j].z;
                        acc[i][j] += af[i].w * bf[j].w;
                    }
            }
        }
        wgsync(wg);     // all done with smem before next steal overwrites

        float* outp = C + (size_t)z * NNODES * Ncols;
#pragma unroll
        for (int i = 0; i < 4; i++)
#pragma unroll
            for (int j = 0; j < 4; j++)
                outp[(size_t)(m0 + ty + 16 * i) * Ncols + n0 + tx + 16 * j] = acc[i][j];
    }
}

// ----------------------------------------------------------------------------
// Pipelined aggregation GEMM 64x64, stealing. alpha built on the fly.
// ----------------------------------------------------------------------------
__device__ void ph_gemm_agg(const float* __restrict__ Z, float* __restrict__ C,
                            const float* __restrict__ ssrc, const float* __restrict__ sdst,
                            const float* __restrict__ Af, const float* __restrict__ Cf,
                            const float* __restrict__ Bp, const float* __restrict__ Dp,
                            int ldz, int hd, int gx, int gy, int nsplit, int H,
                            int klen, int ldc, unsigned* tick,
                            int ltid, int wg, float* gsm)
{
    float* Asb = gsm;              // 2 * 1088
    float* Zs  = gsm + 2176;       // 2 * 1088
    float* Ex  = gsm + 4352;       // 192
    const int tx = ltid & 15, ty = ltid >> 4;
    const int zrow = ltid >> 4, zf4 = ltid & 15;
    const int ail = ltid >> 4, aj4 = (ltid & 15) * 4;
    const int jobs_per_h = gx * gy * nsplit;
    const int njobs = H * jobs_per_h;
    const int nch = klen >> 4;

    for (;;) {
        const int job = steal(tick, njobs, ltid, wg, gsm);
        if (job < 0) break;
        const int h = job / jobs_per_h;
        int rem = job % jobs_per_h;
        const int z = rem / (gx * gy); rem %= gx * gy;
        const int by = rem / gx, bx = rem % gx;
        const int m0 = by * 64, ncol0 = h * hd + bx * 64, kstart = z * klen;
        const float* ss = ssrc + h * NNODES;
        const float* af = Af + h * NNODES;
        const float* cf = Cf + h * NNODES;

        auto build = [&](int cc, float* dst) {
            int ig = kstart + cc * 16 + ail;
            float ssv = ss[ig], afv = af[ig], cfv = cf[ig];
            int jj = aj4;
            float4 w;
            float x0 = ssv + Ex[jj + 0];
            float x1 = ssv + Ex[jj + 1];
            float x2 = ssv + Ex[jj + 2];
            float x3 = ssv + Ex[jj + 3];
            w.x = x0 > 0.f ? afv * Ex[64 + jj + 0] : cfv * Ex[128 + jj + 0];
            w.y = x1 > 0.f ? afv * Ex[64 + jj + 1] : cfv * Ex[128 + jj + 1];
            w.z = x2 > 0.f ? afv * Ex[64 + jj + 2] : cfv * Ex[128 + jj + 2];
            w.w = x3 > 0.f ? afv * Ex[64 + jj + 3] : cfv * Ex[128 + jj + 3];
            if (ig == m0 + jj + 0) w.x = 0.f;
            if (ig == m0 + jj + 1) w.y = 0.f;
            if (ig == m0 + jj + 2) w.z = 0.f;
            if (ig == m0 + jj + 3) w.w = 0.f;
            *(float4*)&dst[ail * 68 + aj4] = w;
        };

        if (ltid < 64) {
            int j = m0 + ltid;
            Ex[ltid]       = sdst[h * NNODES + j];
            Ex[64 + ltid]  = Bp[h * NNODES + j];
            Ex[128 + ltid] = Dp[h * NNODES + j];
        }
        wgsync(wg);                         // Ex visible to ALL threads

        build(0, Asb);
        const float* srcZ = Z + (size_t)(kstart + zrow) * ldz + ncol0 + zf4 * 4;
        const unsigned dstZ = su32(&Zs[zrow * 68 + zf4 * 4]);
        cpa16(dstZ, srcZ);
        cpcommit();

        float acc[4][4];
#pragma unroll
        for (int i = 0; i < 4; i++)
#pragma unroll
            for (int j = 0; j < 4; j++) acc[i][j] = 0.f;

        for (int c = 0; c < nch; c++) {
            const int cb = c & 1;
            cpwait0();
            wgsync(wg);
            if (c + 1 < nch) {
                cpa16(dstZ + (cb ^ 1) * 4352, srcZ + (size_t)(c + 1) * 16 * ldz);
                cpcommit();
                build(c + 1, Asb + (cb ^ 1) * 1088);
            }
            const float* Ab = Asb + cb * 1088;
            const float* Zb = Zs  + cb * 1088;
#pragma unroll
            for (int kk = 0; kk < 16; kk++) {
                float4 a = *(const float4*)&Ab[kk * 68 + ty * 4];
                float4 b = *(const float4*)&Zb[kk * 68 + tx * 4];
                float a4[4] = {a.x, a.y, a.z, a.w};
                float b4[4] = {b.x, b.y, b.z, b.w};
#pragma unroll
                for (int i = 0; i < 4; i++)
#pragma unroll
                    for (int j = 0; j < 4; j++) acc[i][j] += a4[i] * b4[j];
            }
        }
        wgsync(wg);

        float* outp = C + (size_t)z * NNODES * ldc;
#pragma unroll
        for (int i = 0; i < 4; i++)
#pragma unroll
            for (int j = 0; j < 4; j++)
                outp[(size_t)(m0 + ty * 4 + i) * ldc + ncol0 + tx * 4 + j] = acc[i][j];
    }
}

// ----------------------------------------------------------------------------
// fc1 GEMM with softmax folded into A build, stealing (384 jobs, klen 48)
// ----------------------------------------------------------------------------
__device__ void ph_gemm_fc1(const float* __restrict__ h2m, const float* __restrict__ mxc,
                            const float* __restrict__ invc, const float* __restrict__ Bw,
                            float* __restrict__ C, unsigned* tick,
                            int ltid, int wg, float* gsm)
{
    float* As = gsm;
    float* Bs = gsm + 2560;
    const int tx = ltid & 15, ty = ltid >> 4;
    const int row = ltid >> 2, kq = (ltid & 3) * 4;
    const int njobs = 384;
    const int nch = 3;

    for (;;) {
        const int job = steal(tick, njobs, ltid, wg, gsm);
        if (job < 0) break;
        const int z = job / 24;
        const int rem = job % 24;
        const int by = rem / 3, bx = rem % 3;
        const int m0 = by * 64, n0 = bx * 64, kstart = z * 48;

        const unsigned dstB = su32(&Bs[row * RS + kq]);
        const float* srcB = Bw + (size_t)(n0 + row) * IND + kstart + kq;
        const float* srcA = h2m + (size_t)(m0 + row) * IND + kstart + kq;

        float acc[4][4];
#pragma unroll
        for (int i = 0; i < 4; i++)
#pragma unroll
            for (int j = 0; j < 4; j++) acc[i][j] = 0.f;

        cpa16(dstB, srcB);
        cpcommit();
        {
            float4 raw = *(const float4*)srcA;
            float4 mx  = *(const float4*)&mxc[kstart + kq];
            float4 iv  = *(const float4*)&invc[kstart + kq];
            float4 v;
            v.x = __expf(raw.x - mx.x) * iv.x;
            v.y = __expf(raw.y - mx.y) * iv.y;
            v.z = __expf(raw.z - mx.z) * iv.z;
            v.w = __expf(raw.w - mx.w) * iv.w;
            *(float4*)&As[row * RS + kq] = v;
        }

        for (int c = 0; c < nch; c++) {
            const int cb = c & 1;
            cpwait0();
            wgsync(wg);
            float4 raw;
            const bool pre = (c + 1 < nch);
            if (pre) {
                cpa16(dstB + (cb ^ 1) * 5120u, srcB + (c + 1) * 16);
                cpcommit();
                raw = *(const float4*)(srcA + (c + 1) * 16);
            }
            const float* Ab = As + cb * 1280;
            const float* Bb = Bs + cb * 1280;
#pragma unroll
            for (int q = 0; q < 4; q++) {
                float4 af[4], bf[4];
#pragma unroll
                for (int i = 0; i < 4; i++)
                    af[i] = *(const float4*)&Ab[(ty + 16 * i) * RS + q * 4];
#pragma unroll
                for (int j = 0; j < 4; j++)
                    bf[j] = *(const float4*)&Bb[(tx + 16 * j) * RS + q * 4];
#pragma unroll
                for (int i = 0; i < 4; i++)
#pragma unroll
                    for (int j = 0; j < 4; j++) {
                        acc[i][j] += af[i].x * bf[j].x;
                        acc[i][j] += af[i].y * bf[j].y;
                        acc[i][j] += af[i].z * bf[j].z;
                        acc[i][j] += af[i].w * bf[j].w;
                    }
            }
            if (pre) {
                const int kg = kstart + (c + 1) * 16 + kq;
                float4 mx = *(const float4*)&mxc[kg];
                float4 iv = *(const float4*)&invc[kg];
                float4 v;
                v.x = __expf(raw.x - mx.x) * iv.x;
                v.y = __expf(raw.y - mx.y) * iv.y;
                v.z = __expf(raw.z - mx.z) * iv.z;
                v.w = __expf(raw.w - mx.w) * iv.w;
                *(float4*)&As[(cb ^ 1) * 1280 + row * RS + kq] = v;
            }
        }
        wgsync(wg);

        float* outp = C + (size_t)z * NNODES * KCC;
#pragma unroll
        for (int i = 0; i < 4; i++)
#pragma unroll
            for (int j = 0; j < 4; j++)
                outp[(size_t)(m0 + ty + 16 * i) * KCC + n0 + tx + 16 * j] = acc[i][j];
    }
}

// ----------------------------------------------------------------------------
// Fused combine + layer1 scores. Block (768 thr) = 3 rows of z1 per iteration.
// ----------------------------------------------------------------------------
__device__ void ph_combine_scores1(const float* __restrict__ part, int nparts,
                                   const float* __restrict__ a1,
                                   float* __restrict__ z1,
                                   float* __restrict__ ssrc, float* __restrict__ sdst,
                                   float* smblk)
{
    const int tid = threadIdx.x;
    const int total = NNODES * HD1;
    const int d = tid & 255, h = d >> 6, l = d & 63;
    const float a_s = a1[h * 128 + l];
    const float a_d = a1[h * 128 + 64 + l];

    for (int base = blockIdx.x * NT; base < total; base += gridDim.x * NT) {
        const int idx = base + tid;
        float v = 0.f;
        if (idx < total) {
            for (int p = 0; p < nparts; p++) v += part[(size_t)p * total + idx];
            z1[idx] = v;
        }
        float s1 = v * a_s, s2 = v * a_d;
#pragma unroll
        for (int o = 16; o; o >>= 1) {
            s1 += __shfl_xor_sync(0xffffffffu, s1, o);
            s2 += __shfl_xor_sync(0xffffffffu, s2, o);
        }
        const int w = tid >> 5;
        if ((tid & 31) == 0) { smblk[w] = s1; smblk[24 + w] = s2; }
        __syncthreads();
        if (tid < 12) {
            float t1 = smblk[2 * tid] + smblk[2 * tid + 1];
            float t2 = smblk[24 + 2 * tid] + smblk[24 + 2 * tid + 1];
            int row = (base >> 8) + (tid >> 2);
            int hh = tid & 3;
            if (row < NNODES) {
                ssrc[hh * NNODES + row] = t1;
                sdst[hh * NNODES + row] = t2;
            }
        }
        __syncthreads();
    }
}

// ----------------------------------------------------------------------------
// Fused combine + layer2 scores. Block = exactly 1 row of z2 per iteration.
// ----------------------------------------------------------------------------
__device__ void ph_combine_scores2(const float* __restrict__ part, int nparts,
                                   const float* __restrict__ a2,
                                   float* __restrict__ z2,
                                   float* __restrict__ ssrc, float* __restrict__ sdst,
                                   float* smblk)
{
    const int tid = threadIdx.x;
    const int total = NNODES * IND;
    const float a_s = a2[tid];
    const float a_d = a2[IND + tid];

    for (int base = blockIdx.x * NT; base < total; base += gridDim.x * NT) {
        const int idx = base + tid;
        float v = 0.f;
        for (int p = 0; p < nparts; p++) v += part[(size_t)p * total + idx];
        z2[idx] = v;
        float s1 = v * a_s, s2 = v * a_d;
#pragma unroll
        for (int o = 16; o; o >>= 1) {
            s1 += __shfl_xor_sync(0xffffffffu, s1, o);
            s2 += __shfl_xor_sync(0xffffffffu, s2, o);
        }
        const int w = tid >> 5;
        if ((tid & 31) == 0) { smblk[w] = s1; smblk[24 + w] = s2; }
        __syncthreads();
        if (tid == 0) {
            float t1 = 0.f, t2 = 0.f;
            for (int q = 0; q < 24; q++) { t1 += smblk[q]; t2 += smblk[24 + q]; }
            const int row = base / IND;
            ssrc[row] = t1;
            sdst[row] = t2;
        }
        __syncthreads();
    }
}

// ----------------------------------------------------------------------------
// Fused fc1 combine + bias + relu + column-sum (atomic). Block = 4 rows of r.
// ----------------------------------------------------------------------------
__device__ void ph_combine_relu_colsum(const float* __restrict__ part, int nparts,
                                       const float* __restrict__ bias,
                                       float* __restrict__ r, float* smblk)
{
    const int tid = threadIdx.x;
    const int total = NNODES * KCC;
    const float b = bias[tid % KCC];

    for (int base = blockIdx.x * NT; base < total; base += gridDim.x * NT) {
        const int idx = base + tid;
        float v = 0.f;
        for (int p = 0; p < nparts; p++) v += part[(size_t)p * total + idx];
        v = fmaxf(v + b, 0.f);
        r[idx] = v;
        smblk[tid] = v;
        __syncthreads();
        if (tid < KCC)
            atomicAdd(&g_rsum[tid],
                      smblk[tid] + smblk[tid + KCC] + smblk[tid + 2 * KCC] +
                      smblk[tid + 3 * KCC]);
        __syncthreads();
    }
}

// ----------------------------------------------------------------------------
// Plain combine (ELU / none), vectorized float4
// ----------------------------------------------------------------------------
__device__ void ph_combine(float* __restrict__ out, const float* __restrict__ part,
                           int nparts, int total, int act)
{
    const int total4 = total / 4;
    const float4* part4 = (const float4*)part;
    for (int q = blockIdx.x * NT + threadIdx.x; q < total4; q += gridDim.x * NT) {
        float4 s = make_float4(0.f, 0.f, 0.f, 0.f);
        for (int p = 0; p < nparts; p++) {
            float4 v = part4[(size_t)p * total4 + q];
            s.x += v.x; s.y += v.y; s.z += v.z; s.w += v.w;
        }
        if (act == 2) {
            s.x = s.x > 0.f ? s.x : expm1f(s.x);
            s.y = s.y > 0.f ? s.y : expm1f(s.y);
            s.z = s.z > 0.f ? s.z : expm1f(s.z);
            s.w = s.w > 0.f ? s.w : expm1f(s.w);
        }
        *(float4*)&out[q * 4] = s;
    }
}

// ----------------------------------------------------------------------------
// Separable-softmax stats (static mapping; 32 / 8 jobs)
// ----------------------------------------------------------------------------
__device__ void ph_stats(const float* __restrict__ ssrc, const float* __restrict__ sdst,
                         float* __restrict__ Af, float* __restrict__ Cf,
                         float* __restrict__ Bpg, float* __restrict__ Dpg,
                         int H, int ltid, int wg, int grp, int ngrp, float* gsm)
{
    float* ss  = gsm;
    float* aa  = gsm + 512;
    float* cc  = gsm + 1024;
    float* rm1 = gsm + 1536;
    float* rm2 = gsm + 1792;
    int*   ri1 = (int*)(gsm + 2048);
    const int cpj = NNODES / 64;
    const int njobs = H * cpj;

    for (int job = grp; job < njobs; job += ngrp) {
        const int h = job / cpj, jc = job % cpj;
        wgsync(wg);
        for (int i = ltid; i < NNODES; i += GSZ) ss[i] = ssrc[h * NNODES + i];
        wgsync(wg);

        float m1 = -1e30f, m2 = -1e30f; int i1 = -1;
        for (int i = ltid; i < NNODES; i += GSZ) {
            float v = ss[i];
            if (v > m1) { m2 = m1; m1 = v; i1 = i; }
            else if (v > m2) m2 = v;
        }
        rm1[ltid] = m1; rm2[ltid] = m2; ri1[ltid] = i1;
        wgsync(wg);
        if (ltid < 32) {
            float a1 = rm1[ltid], a2 = rm2[ltid]; int ai = ri1[ltid];
            for (int t = ltid + 32; t < GSZ; t += 32) {
                float b1 = rm1[t], b2 = rm2[t];
                if (b1 > a1) { a2 = fmaxf(a1, b2); a1 = b1; ai = ri1[t]; }
                else         { a2 = fmaxf(a2, b1); }
            }
            rm1[ltid] = a1; rm2[ltid] = a2; ri1[ltid] = ai;
        }
        wgsync(wg);
        if (ltid == 0) {
            float a1 = rm1[0], a2 = rm2[0]; int ai = ri1[0];
            for (int t = 1; t < 32; t++) {
                float b1 = rm1[t], b2 = rm2[t];
                if (b1 > a1) { a2 = fmaxf(a1, b2); a1 = b1; ai = ri1[t]; }
                else         { a2 = fmaxf(a2, b1); }
            }
            rm1[0] = a1; rm2[0] = a2; ri1[0] = ai;
        }
        wgsync(wg);
        const float Ms = rm1[0], M2 = rm2[0];
        const int iarg = ri1[0];

        for (int i = ltid; i < NNODES; i += GSZ) {
            float dd = ss[i] - Ms;
            aa[i] = __expf(dd);
            cc[i] = __expf(0.01f * dd);
        }
        wgsync(wg);
        if (jc == 0) {
            for (int i = ltid; i < NNODES; i += GSZ) {
                Af[h * NNODES + i] = aa[i];
                Cf[h * NNODES + i] = cc[i];
            }
        }

        const int wid = ltid >> 5, lane = ltid & 31;
        for (int jj = wid; jj < 64; jj += 8) {
            int j = jc * 64 + jj;
            float sd = sdst[h * NNODES + j];
            float smx = (j == iarg) ? M2 : Ms;
            float t0 = smx + sd;
            float mxj = t0 > 0.f ? t0 : 0.01f * t0;
            float Bj = __expf(Ms + sd - mxj);
            float Dj = __expf(0.01f * (Ms + sd) - mxj);
            float ssum = 0.f;
            for (int i = lane; i < NNODES; i += 32) {
                if (i == j) continue;
                float x = ss[i] + sd;
                ssum += (x > 0.f) ? aa[i] * Bj : cc[i] * Dj;
            }
#pragma unroll
            for (int o = 16; o; o >>= 1) ssum += __shfl_xor_sync(0xffffffffu, ssum, o);
            if (lane == 0) {
                float inv = 1.f / ssum;
                Bpg[h * NNODES + j] = Bj * inv;
                Dpg[h * NNODES + j] = Dj * inv;
            }
        }
    }
}

// ----------------------------------------------------------------------------
// Column softmax stats: 48 jobs x 16 features; 16 thr/col, serial depth 32.
// ----------------------------------------------------------------------------
__device__ void ph_colstats(const float* __restrict__ h2,
                            float* __restrict__ mxc, float* __restrict__ invc,
                            int ltid, int wg, int grp, int ngrp, float* gsm)
{
    float* red  = gsm;        // 256
    float* red2 = gsm + 256;  // 256
    const int fl = ltid & 15, rg = ltid >> 4;   // 16 cols x 16 row-groups
    for (int job = grp; job < IND / 16; job += ngrp) {
        const int f = job * 16 + fl;
        wgsync(wg);
        float m = -1e30f;
        for (int r0 = rg; r0 < NNODES; r0 += 16) m = fmaxf(m, h2[(size_t)r0 * IND + f]);
        red[rg * 16 + fl] = m;
        wgsync(wg);
        if (rg == 0) {
            float mm = red[fl];
#pragma unroll
            for (int g = 1; g < 16; g++) mm = fmaxf(mm, red[g * 16 + fl]);
            red[fl] = mm;
        }
        wgsync(wg);
        const float mf = red[fl];
        float s = 0.f;
        for (int r0 = rg; r0 < NNODES; r0 += 16) s += __expf(h2[(size_t)r0 * IND + f] - mf);
        red2[rg * 16 + fl] = s;
        wgsync(wg);
        if (rg == 0) {
            float t = 0.f;
#pragma unroll
            for (int g = 0; g < 16; g++) t += red2[g * 16 + fl];
            mxc[f] = mf;
            invc[f] = 1.f / t;
        }
    }
}

// ----------------------------------------------------------------------------
// fc2: warp per output
// ----------------------------------------------------------------------------
__device__ void ph_fc2(const float* __restrict__ rsum, const float* __restrict__ w,
                       const float* __restrict__ b, float* __restrict__ out)
{
    const int lane = threadIdx.x & 31;
    const int gw = blockIdx.x * (NT / 32) + (threadIdx.x >> 5);
    const int nw = gridDim.x * (NT / 32);
    for (int o = gw; o < OUTDIM; o += nw) {
        float s = 0.f;
        for (int k = lane; k < KCC; k += 32) s += rsum[k] * w[(size_t)o * KCC + k];
#pragma unroll
        for (int of = 16; of; of >>= 1) s += __shfl_xor_sync(0xffffffffu, s, of);
        if (lane == 0) out[o] = (float)NNODES * b[o] + s;
    }
}

// ----------------------------------------------------------------------------
// Persistent mega-kernel
// ----------------------------------------------------------------------------
__global__ void __launch_bounds__(NT, 1)
gat_mega(const float* __restrict__ X,  const float* __restrict__ W1,
         const float* __restrict__ a1, const float* __restrict__ W2,
         const float* __restrict__ a2, const float* __restrict__ fc1w,
         const float* __restrict__ fc1b, const float* __restrict__ fc2w,
         const float* __restrict__ fc2b, float* __restrict__ out)
{
    extern __shared__ float sm[];
    const int wg = threadIdx.x >> 8;
    const int ltid = threadIdx.x & 255;
    float* gsm = sm + wg * SMG;
    const int grp = wg * gridDim.x + blockIdx.x;
    const int ngrp = gridDim.x * NG;

    // INIT: reset tickets + rsum
    if (blockIdx.x == 0) {
        if (threadIdx.x < 8) g_tick[threadIdx.x] = 0;
        if (threadIdx.x >= 32 && threadIdx.x < 32 + KCC) g_rsum[threadIdx.x - 32] = 0.f;
    }
    gridbar();
    // P0: z1 partials = X @ W1^T, split 12 (384 jobs)
    ph_gemm_abt(X, W1, g_part, HD1, IND, 64, HD1 / 64, NNODES / 64, 12,
                &g_tick[0], ltid, wg, gsm);
    gridbar();
    // P1: combine -> z1 + layer1 scores (fused)
    ph_combine_scores1(g_part, 12, a1, g_z1, g_ssrc, g_sdst, sm);
    gridbar();
    // P2: layer1 stats
    ph_stats(g_ssrc, g_sdst, g_Af, g_Cf, g_Bp, g_Dp, NHEAD, ltid, wg, grp, ngrp, gsm);
    gridbar();
    // P3: agg1 partials, split 8 (256 jobs)
    ph_gemm_agg(g_z1, g_part, g_ssrc, g_sdst, g_Af, g_Cf, g_Bp, g_Dp,
                HD1, HIDD, 1, NNODES / 64, 8, NHEAD, 64, HD1,
                &g_tick[1], ltid, wg, gsm);
    gridbar();
    // P4: combine + ELU -> h1
    ph_combine(g_h1, g_part, 8, NNODES * HD1, 2);
    gridbar();
    // P5: z2 partials = h1 @ W2^T, split 4 (384 jobs)
    ph_gemm_abt(g_h1, W2, g_part, IND, HD1, 64, IND / 64, NNODES / 64, 4,
                &g_tick[2], ltid, wg, gsm);
    gridbar();
    // P6: combine -> z2 + layer2 scores (fused)
    ph_combine_scores2(g_part, 4, a2, g_z2, g_ssrc, g_sdst, sm);
    gridbar();
    // P7: layer2 stats
    ph_stats(g_ssrc, g_sdst, g_Af, g_Cf, g_Bp, g_Dp, 1, ltid, wg, grp, ngrp, gsm);
    gridbar();
    // P8: agg2 partials, split 4 (384 jobs, klen 128)
    ph_gemm_agg(g_z2, g_part, g_ssrc, g_sdst, g_Af, g_Cf, g_Bp, g_Dp,
                IND, 0, IND / 64, NNODES / 64, 4, 1, 128, IND,
                &g_tick[3], ltid, wg, gsm);
    gridbar();
    // P9: combine -> h2
    ph_combine(g_h2, g_part, 4, NNODES * IND, 0);
    gridbar();
    // P10: column softmax stats (48 jobs)
    ph_colstats(g_h2, g_mxc, g_invc, ltid, wg, grp, ngrp, gsm);
    gridbar();
    // P11: fc1 partials = softmax(h2) @ fc1_w^T (exp fused), 384 jobs
    ph_gemm_fc1(g_h2, g_mxc, g_invc, fc1w, g_part, &g_tick[4], ltid, wg, gsm);
    gridbar();
    // P12: combine + bias + relu -> r, + atomic column sum (fused)
    ph_combine_relu_colsum(g_part, 16, fc1b, g_r, sm);
    gridbar();
    // P13: fc2 -> out
    ph_fc2(g_rsum, fc2w, fc2b, out);
}

// ----------------------------------------------------------------------------
// Launch
// ----------------------------------------------------------------------------
extern "C" void kernel_launch(void* const* d_in, const int* in_sizes, int n_in,
                              void* d_out, int out_size)
{
    const float* X     = (const float*)d_in[0];
    const float* W1    = (const float*)d_in[1];
    const float* a1    = (const float*)d_in[2];
    const float* W2    = (const float*)d_in[3];
    const float* a2    = (const float*)d_in[4];
    const float* fc1_w = (const float*)d_in[5];
    const float* fc1_b = (const float*)d_in[6];
    const float* fc2_w = (const float*)d_in[7];
    const float* fc2_b = (const float*)d_in[8];

    int sms = 148;
    cudaDeviceGetAttribute(&sms, cudaDevAttrMultiProcessorCount, 0);

    const size_t smbytes = (size_t)NG * SMG * sizeof(float);   // ~61 KB
    cudaFuncSetAttribute(gat_mega, cudaFuncAttributeMaxDynamicSharedMemorySize,
                         (int)smbytes);

    gat_mega<<<sms, NT, smbytes>>>(X, W1, a1, W2, a2, fc1_w, fc1_b, fc2_w, fc2_b,
                                   (float*)d_out);
}

// round 14
// speedup vs baseline: 1.1387x; 1.0615x over previous
#include <cuda_runtime.h>
#include <math.h>

#define NNODES 512
#define IND    768
#define HIDD   64
#define NHEAD  4
#define HD1    256
#define KCC    192
#define OUTDIM 256
#define NT     768
#define NG     3
#define GSZ    256
#define SMG    5184         // smem floats per warpgroup
#define RS     20           // smem row stride (16 k + 4 pad)
#define JOBSLOT 5120        // per-group smem job ticket slot

// ----------------------------------------------------------------------------
// Device scratch
// ----------------------------------------------------------------------------
__device__ __align__(16) float g_z1[NNODES * HD1];
__device__ __align__(16) float g_h1[NNODES * HD1];
__device__ __align__(16) float g_z2[NNODES * IND];
__device__ __align__(16) float g_h2[NNODES * IND];
__device__ __align__(16) float g_r [NNODES * KCC];
__device__ __align__(16) float g_part[4 * NNODES * IND];
__device__ __align__(16) float g_ssrc[NHEAD * NNODES];
__device__ __align__(16) float g_sdst[NHEAD * NNODES];
__device__ __align__(16) float g_Af[NHEAD * NNODES];
__device__ __align__(16) float g_Cf[NHEAD * NNODES];
__device__ __align__(16) float g_Bp[NHEAD * NNODES];
__device__ __align__(16) float g_Dp[NHEAD * NNODES];
__device__ __align__(16) float g_mxc[IND], g_invc[IND];
__device__ float g_rsum[KCC];
__device__ unsigned g_tick[8];
__device__ unsigned g_cnt8[8];
__device__ unsigned g_root = 0;
__device__ volatile unsigned g_bargen = 0;

// ----------------------------------------------------------------------------
// Barriers + cp.async helpers
// ----------------------------------------------------------------------------
__device__ __forceinline__ void wgsync(int wg) {
    asm volatile("bar.sync %0, %1;" :: "r"(wg + 1), "n"(GSZ) : "memory");
}

__device__ __forceinline__ void gridbar() {
    __syncthreads();
    if (threadIdx.x == 0) {
        __threadfence();
        const unsigned gen = g_bargen;
        const unsigned b = blockIdx.x & 7u;
        const unsigned bsz = (gridDim.x >> 3) + (((gridDim.x & 7u) > b) ? 1u : 0u);
        if (atomicAdd(&g_cnt8[b], 1u) == bsz - 1u) {
            atomicExch(&g_cnt8[b], 0u);
            __threadfence();
            if (atomicAdd(&g_root, 1u) == 7u) {
                atomicExch(&g_root, 0u);
                __threadfence();
                atomicAdd((unsigned*)&g_bargen, 1u);
            }
        }
        while (g_bargen == gen) { __nanosleep(32); }
        __threadfence();
    }
    __syncthreads();
}

__device__ __forceinline__ unsigned su32(const void* p) {
    return (unsigned)__cvta_generic_to_shared(p);
}
__device__ __forceinline__ void cpa16(unsigned d, const void* s) {
    asm volatile("cp.async.cg.shared.global [%0], [%1], 16;" :: "r"(d), "l"(s));
}
__device__ __forceinline__ void cpcommit() { asm volatile("cp.async.commit_group;"); }
__device__ __forceinline__ void cpwait0()  { asm volatile("cp.async.wait_group 0;"); }

__device__ __forceinline__ int steal(unsigned* tick, int njobs, int ltid, int wg,
                                     float* gsm)
{
    volatile unsigned* slot = (volatile unsigned*)(gsm + JOBSLOT);
    if (ltid == 0) *slot = atomicAdd(tick, 1u);
    wgsync(wg);
    int job = (int)*slot;
    return (job < njobs) ? job : -1;
}

// ----------------------------------------------------------------------------
// TF32 MMA helpers (m16n8k8), split-precision (hi + lo) for ~fp32 accuracy
// ----------------------------------------------------------------------------
__device__ __forceinline__ unsigned f2tf(float x) {
    unsigned r; asm("cvt.rna.tf32.f32 %0, %1;" : "=r"(r) : "f"(x)); return r;
}
__device__ __forceinline__ void mma8(float* c, unsigned a0, unsigned a1,
                                     unsigned a2, unsigned a3,
                                     unsigned b0, unsigned b1) {
    asm volatile("mma.sync.aligned.m16n8k8.row.col.f32.tf32.tf32.f32 "
                 "{%0,%1,%2,%3}, {%4,%5,%6,%7}, {%8,%9}, {%0,%1,%2,%3};"
                 : "+f"(c[0]), "+f"(c[1]), "+f"(c[2]), "+f"(c[3])
                 : "r"(a0), "r"(a1), "r"(a2), "r"(a3), "r"(b0), "r"(b1));
}

// 16x32 warp-tile over one k16 chunk. Ab: [m][k] stride RS. Bb: [n][k] stride RS.
__device__ __forceinline__ void mma_chunk_abt(const float* Ab, const float* Bb,
                                              int wm, int wn, int g, int t,
                                              float acc[4][4])
{
#pragma unroll
    for (int s = 0; s < 2; s++) {
        const float* Ar = Ab + (16 * wm) * RS + 8 * s + t;
        float a0f = Ar[g * RS],     a1f = Ar[(g + 8) * RS];
        float a2f = Ar[g * RS + 4], a3f = Ar[(g + 8) * RS + 4];
        unsigned ah0 = f2tf(a0f), ah1 = f2tf(a1f), ah2 = f2tf(a2f), ah3 = f2tf(a3f);
        unsigned al0 = __float_as_uint(a0f - __uint_as_float(ah0));
        unsigned al1 = __float_as_uint(a1f - __uint_as_float(ah1));
        unsigned al2 = __float_as_uint(a2f - __uint_as_float(ah2));
        unsigned al3 = __float_as_uint(a3f - __uint_as_float(ah3));
#pragma unroll
        for (int nf = 0; nf < 4; nf++) {
            const float* Br = Bb + (32 * wn + 8 * nf + g) * RS + 8 * s + t;
            float b0f = Br[0], b1f = Br[4];
            unsigned bh0 = f2tf(b0f), bh1 = f2tf(b1f);
            unsigned bl0 = __float_as_uint(b0f - __uint_as_float(bh0));
            unsigned bl1 = __float_as_uint(b1f - __uint_as_float(bh1));
            mma8(acc[nf], ah0, ah1, ah2, ah3, bh0, bh1);
            mma8(acc[nf], al0, al1, al2, al3, bh0, bh1);
            mma8(acc[nf], ah0, ah1, ah2, ah3, bl0, bl1);
        }
    }
}

// Same but B in [k][n] layout, stride 68 (agg Z tiles)
__device__ __forceinline__ void mma_chunk_agg(const float* Ab, const float* Zb,
                                              int wm, int wn, int g, int t,
                                              float acc[4][4])
{
#pragma unroll
    for (int s = 0; s < 2; s++) {
        const float* Ar = Ab + (16 * wm) * RS + 8 * s + t;
        float a0f = Ar[g * RS],     a1f = Ar[(g + 8) * RS];
        float a2f = Ar[g * RS + 4], a3f = Ar[(g + 8) * RS + 4];
        unsigned ah0 = f2tf(a0f), ah1 = f2tf(a1f), ah2 = f2tf(a2f), ah3 = f2tf(a3f);
        unsigned al0 = __float_as_uint(a0f - __uint_as_float(ah0));
        unsigned al1 = __float_as_uint(a1f - __uint_as_float(ah1));
        unsigned al2 = __float_as_uint(a2f - __uint_as_float(ah2));
        unsigned al3 = __float_as_uint(a3f - __uint_as_float(ah3));
#pragma unroll
        for (int nf = 0; nf < 4; nf++) {
            const float* Br = Zb + (8 * s + t) * 68 + 32 * wn + 8 * nf + g;
            float b0f = Br[0], b1f = Br[4 * 68];
            unsigned bh0 = f2tf(b0f), bh1 = f2tf(b1f);
            unsigned bl0 = __float_as_uint(b0f - __uint_as_float(bh0));
            unsigned bl1 = __float_as_uint(b1f - __uint_as_float(bh1));
            mma8(acc[nf], ah0, ah1, ah2, ah3, bh0, bh1);
            mma8(acc[nf], al0, al1, al2, al3, bh0, bh1);
            mma8(acc[nf], ah0, ah1, ah2, ah3, bl0, bl1);
        }
    }
}

__device__ __forceinline__ void store_tile(float* outp, int ld, int m0, int n0,
                                           int wm, int wn, int g, int t,
                                           float acc[4][4])
{
    const int r0 = m0 + 16 * wm + g;
    const int cb = n0 + 32 * wn + 2 * t;
#pragma unroll
    for (int nf = 0; nf < 4; nf++) {
        *(float2*)&outp[(size_t)r0 * ld + cb + 8 * nf] =
            make_float2(acc[nf][0], acc[nf][1]);
        *(float2*)&outp[(size_t)(r0 + 8) * ld + cb + 8 * nf] =
            make_float2(acc[nf][2], acc[nf][3]);
    }
}

// ----------------------------------------------------------------------------
// Pipelined SGEMM 64x64 via TF32 MMA, chunk=16, one barrier/chunk, stealing.
// ----------------------------------------------------------------------------
__device__ void ph_gemm_abt(const float* __restrict__ A, const float* __restrict__ B,
                            float* __restrict__ C, int Ncols, int K_ld, int klen,
                            int gx, int gy, int nsplit, unsigned* tick,
                            int ltid, int wg, float* gsm)
{
    float* As = gsm;                 // 2 * 1280
    float* Bs = gsm + 2560;          // 2 * 1280
    const int w = ltid >> 5, wm = w >> 1, wn = w & 1;
    const int lane = ltid & 31, g = lane >> 2, t = lane & 3;
    const int isB  = ltid >> 7;
    const int lrow = (ltid & 127) >> 1;
    const int lh   = ltid & 1;
    const int njobs = gx * gy * nsplit;
    const int nch = klen >> 4;

    for (;;) {
        const int job = steal(tick, njobs, ltid, wg, gsm);   // wgsync inside
        if (job < 0) break;
        const int z = job / (gx * gy);
        const int rem = job % (gx * gy);
        const int by = rem / gx, bx = rem % gx;
        const int m0 = by * 64, n0 = bx * 64, kstart = z * klen;

        const float* src0 = isB ? (B + (size_t)(n0 + lrow) * K_ld + kstart + lh * 8)
                                : (A + (size_t)(m0 + lrow) * K_ld + kstart + lh * 8);
        const unsigned dst0 = isB ? su32(&Bs[lrow * RS + lh * 8])
                                  : su32(&As[lrow * RS + lh * 8]);

        float acc[4][4];
#pragma unroll
        for (int i = 0; i < 4; i++)
#pragma unroll
            for (int j = 0; j < 4; j++) acc[i][j] = 0.f;

        cpa16(dst0, src0);
        cpa16(dst0 + 16, src0 + 4);
        cpcommit();

        for (int c = 0; c < nch; c++) {
            const int cb = c & 1;
            cpwait0();
            wgsync(wg);
            if (c + 1 < nch) {
                const unsigned d = dst0 + (cb ^ 1) * 5120;
                const float* s = src0 + (c + 1) * 16;
                cpa16(d, s);
                cpa16(d + 16, s + 4);
                cpcommit();
            }
            mma_chunk_abt(As + cb * 1280, Bs + cb * 1280, wm, wn, g, t, acc);
        }
        wgsync(wg);     // done with smem before next steal overwrites

        store_tile(C + (size_t)z * NNODES * Ncols, Ncols, m0, n0, wm, wn, g, t, acc);
    }
}

// ----------------------------------------------------------------------------
// Aggregation GEMM 64x64 via TF32 MMA; alpha built on the fly in [j][k] layout.
// ----------------------------------------------------------------------------
__device__ void ph_gemm_agg(const float* __restrict__ Z, float* __restrict__ C,
                            const float* __restrict__ ssrc, const float* __restrict__ sdst,
                            const float* __restrict__ Af, const float* __restrict__ Cf,
                            const float* __restrict__ Bp, const float* __restrict__ Dp,
                            int ldz, int hd, int gx, int gy, int nsplit, int H,
                            int klen, int ldc, unsigned* tick,
                            int ltid, int wg, float* gsm)
{
    float* Asb = gsm;              // 2 * 1280 ([j 64][k 16] stride RS)
    float* Zs  = gsm + 2560;       // 2 * 1088 ([k 16][col 64] stride 68)
    float* Ex  = gsm + 4736;       // 192
    const int w = ltid >> 5, wm = w >> 1, wn = w & 1;
    const int lane = ltid & 31, g = lane >> 2, t = lane & 3;
    const int zrow = ltid >> 4, zf4 = ltid & 15;
    const int jrow = ltid >> 2, i4 = (ltid & 3) * 4;
    const int jobs_per_h = gx * gy * nsplit;
    const int njobs = H * jobs_per_h;
    const int nch = klen >> 4;

    for (;;) {
        const int job = steal(tick, njobs, ltid, wg, gsm);
        if (job < 0) break;
        const int h = job / jobs_per_h;
        int rem = job % jobs_per_h;
        const int z = rem / (gx * gy); rem %= gx * gy;
        const int by = rem / gx, bx = rem % gx;
        const int m0 = by * 64, ncol0 = h * hd + bx * 64, kstart = z * klen;
        const float* ss = ssrc + h * NNODES;
        const float* af = Af + h * NNODES;
        const float* cf = Cf + h * NNODES;

        auto build = [&](int cc, float* dst) {
            const int base = kstart + cc * 16 + i4;
            float4 s4 = *(const float4*)&ss[base];
            float4 a4 = *(const float4*)&af[base];
            float4 c4 = *(const float4*)&cf[base];
            const float dj  = Ex[jrow];
            const float bpj = Ex[64 + jrow];
            const float dpj = Ex[128 + jrow];
            const int jg = m0 + jrow;
            float4 wv;
            wv.x = (s4.x + dj > 0.f) ? a4.x * bpj : c4.x * dpj;
            wv.y = (s4.y + dj > 0.f) ? a4.y * bpj : c4.y * dpj;
            wv.z = (s4.z + dj > 0.f) ? a4.z * bpj : c4.z * dpj;
            wv.w = (s4.w + dj > 0.f) ? a4.w * bpj : c4.w * dpj;
            if (base + 0 == jg) wv.x = 0.f;
            if (base + 1 == jg) wv.y = 0.f;
            if (base + 2 == jg) wv.z = 0.f;
            if (base + 3 == jg) wv.w = 0.f;
            *(float4*)&dst[jrow * RS + i4] = wv;
        };

        if (ltid < 64) {
            int j = m0 + ltid;
            Ex[ltid]       = sdst[h * NNODES + j];
            Ex[64 + ltid]  = Bp[h * NNODES + j];
            Ex[128 + ltid] = Dp[h * NNODES + j];
        }
        wgsync(wg);                         // Ex visible to ALL threads

        build(0, Asb);
        const float* srcZ = Z + (size_t)(kstart + zrow) * ldz + ncol0 + zf4 * 4;
        const unsigned dstZ = su32(&Zs[zrow * 68 + zf4 * 4]);
        cpa16(dstZ, srcZ);
        cpcommit();

        float acc[4][4];
#pragma unroll
        for (int i = 0; i < 4; i++)
#pragma unroll
            for (int j = 0; j < 4; j++) acc[i][j] = 0.f;

        for (int c = 0; c < nch; c++) {
            const int cb = c & 1;
            cpwait0();
            wgsync(wg);
            if (c + 1 < nch) {
                cpa16(dstZ + (cb ^ 1) * 4352, srcZ + (size_t)(c + 1) * 16 * ldz);
                cpcommit();
                build(c + 1, Asb + (cb ^ 1) * 1280);
            }
            mma_chunk_agg(Asb + cb * 1280, Zs + cb * 1088, wm, wn, g, t, acc);
        }
        wgsync(wg);

        store_tile(C + (size_t)z * NNODES * ldc, ldc, m0, ncol0, wm, wn, g, t, acc);
    }
}

// ----------------------------------------------------------------------------
// fc1 GEMM via TF32 MMA with softmax folded into A build (384 jobs, klen 48)
// ----------------------------------------------------------------------------
__device__ void ph_gemm_fc1(const float* __restrict__ h2m, const float* __restrict__ mxc,
                            const float* __restrict__ invc, const float* __restrict__ Bw,
                            float* __restrict__ C, unsigned* tick,
                            int ltid, int wg, float* gsm)
{
    float* As = gsm;
    float* Bs = gsm + 2560;
    const int w = ltid >> 5, wm = w >> 1, wn = w & 1;
    const int lane = ltid & 31, g = lane >> 2, t = lane & 3;
    const int row = ltid >> 2, kq = (ltid & 3) * 4;
    const int njobs = 384;
    const int nch = 3;

    for (;;) {
        const int job = steal(tick, njobs, ltid, wg, gsm);
        if (job < 0) break;
        const int z = job / 24;
        const int rem = job % 24;
        const int by = rem / 3, bx = rem % 3;
        const int m0 = by * 64, n0 = bx * 64, kstart = z * 48;

        const unsigned dstB = su32(&Bs[row * RS + kq]);
        const float* srcB = Bw + (size_t)(n0 + row) * IND + kstart + kq;
        const float* srcA = h2m + (size_t)(m0 + row) * IND + kstart + kq;

        float acc[4][4];
#pragma unroll
        for (int i = 0; i < 4; i++)
#pragma unroll
            for (int j = 0; j < 4; j++) acc[i][j] = 0.f;

        cpa16(dstB, srcB);
        cpcommit();
        {
            float4 raw = *(const float4*)srcA;
            float4 mx  = *(const float4*)&mxc[kstart + kq];
            float4 iv  = *(const float4*)&invc[kstart + kq];
            float4 v;
            v.x = __expf(raw.x - mx.x) * iv.x;
            v.y = __expf(raw.y - mx.y) * iv.y;
            v.z = __expf(raw.z - mx.z) * iv.z;
            v.w = __expf(raw.w - mx.w) * iv.w;
            *(float4*)&As[row * RS + kq] = v;
        }

        for (int c = 0; c < nch; c++) {
            const int cb = c & 1;
            cpwait0();
            wgsync(wg);
            float4 raw;
            const bool pre = (c + 1 < nch);
            if (pre) {
                cpa16(dstB + (cb ^ 1) * 5120u, srcB + (c + 1) * 16);
                cpcommit();
                raw = *(const float4*)(srcA + (c + 1) * 16);
            }
            mma_chunk_abt(As + cb * 1280, Bs + cb * 1280, wm, wn, g, t, acc);
            if (pre) {
                const int kg = kstart + (c + 1) * 16 + kq;
                float4 mx = *(const float4*)&mxc[kg];
                float4 iv = *(const float4*)&invc[kg];
                float4 v;
                v.x = __expf(raw.x - mx.x) * iv.x;
                v.y = __expf(raw.y - mx.y) * iv.y;
                v.z = __expf(raw.z - mx.z) * iv.z;
                v.w = __expf(raw.w - mx.w) * iv.w;
                *(float4*)&As[(cb ^ 1) * 1280 + row * RS + kq] = v;
            }
        }
        wgsync(wg);

        store_tile(C + (size_t)z * NNODES * KCC, KCC, m0, n0, wm, wn, g, t, acc);
    }
}

// ----------------------------------------------------------------------------
// Fused combine + layer1 scores. Block (768 thr) = 3 rows of z1 per iteration.
// ----------------------------------------------------------------------------
__device__ void ph_combine_scores1(const float* __restrict__ part, int nparts,
                                   const float* __restrict__ a1,
                                   float* __restrict__ z1,
                                   float* __restrict__ ssrc, float* __restrict__ sdst,
                                   float* smblk)
{
    const int tid = threadIdx.x;
    const int total = NNODES * HD1;
    const int d = tid & 255, h = d >> 6, l = d & 63;
    const float a_s = a1[h * 128 + l];
    const float a_d = a1[h * 128 + 64 + l];

    for (int base = blockIdx.x * NT; base < total; base += gridDim.x * NT) {
        const int idx = base + tid;
        float v = 0.f;
        if (idx < total) {
            for (int p = 0; p < nparts; p++) v += part[(size_t)p * total + idx];
            z1[idx] = v;
        }
        float s1 = v * a_s, s2 = v * a_d;
#pragma unroll
        for (int o = 16; o; o >>= 1) {
            s1 += __shfl_xor_sync(0xffffffffu, s1, o);
            s2 += __shfl_xor_sync(0xffffffffu, s2, o);
        }
        const int wq = tid >> 5;
        if ((tid & 31) == 0) { smblk[wq] = s1; smblk[24 + wq] = s2; }
        __syncthreads();
        if (tid < 12) {
            float t1 = smblk[2 * tid] + smblk[2 * tid + 1];
            float t2 = smblk[24 + 2 * tid] + smblk[24 + 2 * tid + 1];
            int row = (base >> 8) + (tid >> 2);
            int hh = tid & 3;
            if (row < NNODES) {
                ssrc[hh * NNODES + row] = t1;
                sdst[hh * NNODES + row] = t2;
            }
        }
        __syncthreads();
    }
}

// ----------------------------------------------------------------------------
// Fused combine + layer2 scores. Block = exactly 1 row of z2 per iteration.
// ----------------------------------------------------------------------------
__device__ void ph_combine_scores2(const float* __restrict__ part, int nparts,
                                   const float* __restrict__ a2,
                                   float* __restrict__ z2,
                                   float* __restrict__ ssrc, float* __restrict__ sdst,
                                   float* smblk)
{
    const int tid = threadIdx.x;
    const int total = NNODES * IND;
    const float a_s = a2[tid];
    const float a_d = a2[IND + tid];

    for (int base = blockIdx.x * NT; base < total; base += gridDim.x * NT) {
        const int idx = base + tid;
        float v = 0.f;
        for (int p = 0; p < nparts; p++) v += part[(size_t)p * total + idx];
        z2[idx] = v;
        float s1 = v * a_s, s2 = v * a_d;
#pragma unroll
        for (int o = 16; o; o >>= 1) {
            s1 += __shfl_xor_sync(0xffffffffu, s1, o);
            s2 += __shfl_xor_sync(0xffffffffu, s2, o);
        }
        const int wq = tid >> 5;
        if ((tid & 31) == 0) { smblk[wq] = s1; smblk[24 + wq] = s2; }
        __syncthreads();
        if (tid == 0) {
            float t1 = 0.f, t2 = 0.f;
            for (int q = 0; q < 24; q++) { t1 += smblk[q]; t2 += smblk[24 + q]; }
            const int row = base / IND;
            ssrc[row] = t1;
            sdst[row] = t2;
        }
        __syncthreads();
    }
}

// ----------------------------------------------------------------------------
// Fused fc1 combine + bias + relu + column-sum (atomic). Block = 4 rows of r.
// ----------------------------------------------------------------------------
__device__ void ph_combine_relu_colsum(const float* __restrict__ part, int nparts,
                                       const float* __restrict__ bias,
                                       float* __restrict__ r, float* smblk)
{
    const int tid = threadIdx.x;
    const int total = NNODES * KCC;
    const float b = bias[tid % KCC];

    for (int base = blockIdx.x * NT; base < total; base += gridDim.x * NT) {
        const int idx = base + tid;
        float v = 0.f;
        for (int p = 0; p < nparts; p++) v += part[(size_t)p * total + idx];
        v = fmaxf(v + b, 0.f);
        r[idx] = v;
        smblk[tid] = v;
        __syncthreads();
        if (tid < KCC)
            atomicAdd(&g_rsum[tid],
                      smblk[tid] + smblk[tid + KCC] + smblk[tid + 2 * KCC] +
                      smblk[tid + 3 * KCC]);
        __syncthreads();
    }
}

// ----------------------------------------------------------------------------
// Plain combine (ELU / none), vectorized float4
// ----------------------------------------------------------------------------
__device__ void ph_combine(float* __restrict__ out, const float* __restrict__ part,
                           int nparts, int total, int act)
{
    const int total4 = total / 4;
    const float4* part4 = (const float4*)part;
    for (int q = blockIdx.x * NT + threadIdx.x; q < total4; q += gridDim.x * NT) {
        float4 s = make_float4(0.f, 0.f, 0.f, 0.f);
        for (int p = 0; p < nparts; p++) {
            float4 v = part4[(size_t)p * total4 + q];
            s.x += v.x; s.y += v.y; s.z += v.z; s.w += v.w;
        }
        if (act == 2) {
            s.x = s.x > 0.f ? s.x : expm1f(s.x);
            s.y = s.y > 0.f ? s.y : expm1f(s.y);
            s.z = s.z > 0.f ? s.z : expm1f(s.z);
            s.w = s.w > 0.f ? s.w : expm1f(s.w);
        }
        *(float4*)&out[q * 4] = s;
    }
}

// ----------------------------------------------------------------------------
// Separable-softmax stats (static mapping; 32 / 8 jobs)
// ----------------------------------------------------------------------------
__device__ void ph_stats(const float* __restrict__ ssrc, const float* __restrict__ sdst,
                         float* __restrict__ Af, float* __restrict__ Cf,
                         float* __restrict__ Bpg, float* __restrict__ Dpg,
                         int H, int ltid, int wg, int grp, int ngrp, float* gsm)
{
    float* ss  = gsm;
    float* aa  = gsm + 512;
    float* cc  = gsm + 1024;
    float* rm1 = gsm + 1536;
    float* rm2 = gsm + 1792;
    int*   ri1 = (int*)(gsm + 2048);
    const int cpj = NNODES / 64;
    const int njobs = H * cpj;

    for (int job = grp; job < njobs; job += ngrp) {
        const int h = job / cpj, jc = job % cpj;
        wgsync(wg);
        for (int i = ltid; i < NNODES; i += GSZ) ss[i] = ssrc[h * NNODES + i];
        wgsync(wg);

        float m1 = -1e30f, m2 = -1e30f; int i1 = -1;
        for (int i = ltid; i < NNODES; i += GSZ) {
            float v = ss[i];
            if (v > m1) { m2 = m1; m1 = v; i1 = i; }
            else if (v > m2) m2 = v;
        }
        rm1[ltid] = m1; rm2[ltid] = m2; ri1[ltid] = i1;
        wgsync(wg);
        if (ltid < 32) {
            float a1 = rm1[ltid], a2 = rm2[ltid]; int ai = ri1[ltid];
            for (int tt = ltid + 32; tt < GSZ; tt += 32) {
                float b1 = rm1[tt], b2 = rm2[tt];
                if (b1 > a1) { a2 = fmaxf(a1, b2); a1 = b1; ai = ri1[tt]; }
                else         { a2 = fmaxf(a2, b1); }
            }
            rm1[ltid] = a1; rm2[ltid] = a2; ri1[ltid] = ai;
        }
        wgsync(wg);
        if (ltid == 0) {
            float a1 = rm1[0], a2 = rm2[0]; int ai = ri1[0];
            for (int tt = 1; tt < 32; tt++) {
                float b1 = rm1[tt], b2 = rm2[tt];
                if (b1 > a1) { a2 = fmaxf(a1, b2); a1 = b1; ai = ri1[tt]; }
                else         { a2 = fmaxf(a2, b1); }
            }
            rm1[0] = a1; rm2[0] = a2; ri1[0] = ai;
        }
        wgsync(wg);
        const float Ms = rm1[0], M2 = rm2[0];
        const int iarg = ri1[0];

        for (int i = ltid; i < NNODES; i += GSZ) {
            float dd = ss[i] - Ms;
            aa[i] = __expf(dd);
            cc[i] = __expf(0.01f * dd);
        }
        wgsync(wg);
        if (jc == 0) {
            for (int i = ltid; i < NNODES; i += GSZ) {
                Af[h * NNODES + i] = aa[i];
                Cf[h * NNODES + i] = cc[i];
            }
        }

        const int wid = ltid >> 5, lane = ltid & 31;
        for (int jj = wid; jj < 64; jj += 8) {
            int j = jc * 64 + jj;
            float sd = sdst[h * NNODES + j];
            float smx = (j == iarg) ? M2 : Ms;
            float t0 = smx + sd;
            float mxj = t0 > 0.f ? t0 : 0.01f * t0;
            float Bj = __expf(Ms + sd - mxj);
            float Dj = __expf(0.01f * (Ms + sd) - mxj);
            float ssum = 0.f;
            for (int i = lane; i < NNODES; i += 32) {
                if (i == j) continue;
                float x = ss[i] + sd;
                ssum += (x > 0.f) ? aa[i] * Bj : cc[i] * Dj;
            }
#pragma unroll
            for (int o = 16; o; o >>= 1) ssum += __shfl_xor_sync(0xffffffffu, ssum, o);
            if (lane == 0) {
                float inv = 1.f / ssum;
                Bpg[h * NNODES + j] = Bj * inv;
                Dpg[h * NNODES + j] = Dj * inv;
            }
        }
    }
}

// ----------------------------------------------------------------------------
// Column softmax stats: 48 jobs x 16 features; 16 thr/col, serial depth 32.
// ----------------------------------------------------------------------------
__device__ void ph_colstats(const float* __restrict__ h2,
                            float* __restrict__ mxc, float* __restrict__ invc,
                            int ltid, int wg, int grp, int ngrp, float* gsm)
{
    float* red  = gsm;        // 256
    float* red2 = gsm + 256;  // 256
    const int fl = ltid & 15, rg = ltid >> 4;
    for (int job = grp; job < IND / 16; job += ngrp) {
        const int f = job * 16 + fl;
        wgsync(wg);
        float m = -1e30f;
        for (int r0 = rg; r0 < NNODES; r0 += 16) m = fmaxf(m, h2[(size_t)r0 * IND + f]);
        red[rg * 16 + fl] = m;
        wgsync(wg);
        if (rg == 0) {
            float mm = red[fl];
#pragma unroll
            for (int gq = 1; gq < 16; gq++) mm = fmaxf(mm, red[gq * 16 + fl]);
            red[fl] = mm;
        }
        wgsync(wg);
        const float mf = red[fl];
        float s = 0.f;
        for (int r0 = rg; r0 < NNODES; r0 += 16) s += __expf(h2[(size_t)r0 * IND + f] - mf);
        red2[rg * 16 + fl] = s;
        wgsync(wg);
        if (rg == 0) {
            float tq = 0.f;
#pragma unroll
            for (int gq = 0; gq < 16; gq++) tq += red2[gq * 16 + fl];
            mxc[f] = mf;
            invc[f] = 1.f / tq;
        }
    }
}

// ----------------------------------------------------------------------------
// fc2: warp per output
// ----------------------------------------------------------------------------
__device__ void ph_fc2(const float* __restrict__ rsum, const float* __restrict__ w,
                       const float* __restrict__ b, float* __restrict__ out)
{
    const int lane = threadIdx.x & 31;
    const int gw = blockIdx.x * (NT / 32) + (threadIdx.x >> 5);
    const int nw = gridDim.x * (NT / 32);
    for (int o = gw; o < OUTDIM; o += nw) {
        float s = 0.f;
        for (int k = lane; k < KCC; k += 32) s += rsum[k] * w[(size_t)o * KCC + k];
#pragma unroll
        for (int of = 16; of; of >>= 1) s += __shfl_xor_sync(0xffffffffu, s, of);
        if (lane == 0) out[o] = (float)NNODES * b[o] + s;
    }
}

// ----------------------------------------------------------------------------
// Persistent mega-kernel
// ----------------------------------------------------------------------------
__global__ void __launch_bounds__(NT, 1)
gat_mega(const float* __restrict__ X,  const float* __restrict__ W1,
         const float* __restrict__ a1, const float* __restrict__ W2,
         const float* __restrict__ a2, const float* __restrict__ fc1w,
         const float* __restrict__ fc1b, const float* __restrict__ fc2w,
         const float* __restrict__ fc2b, float* __restrict__ out)
{
    extern __shared__ float sm[];
    const int wg = threadIdx.x >> 8;
    const int ltid = threadIdx.x & 255;
    float* gsm = sm + wg * SMG;
    const int grp = wg * gridDim.x + blockIdx.x;
    const int ngrp = gridDim.x * NG;

    // INIT: reset tickets + rsum
    if (blockIdx.x == 0) {
        if (threadIdx.x < 8) g_tick[threadIdx.x] = 0;
        if (threadIdx.x >= 32 && threadIdx.x < 32 + KCC) g_rsum[threadIdx.x - 32] = 0.f;
    }
    gridbar();
    // P0: z1 partials = X @ W1^T, split 12 (384 jobs)
    ph_gemm_abt(X, W1, g_part, HD1, IND, 64, HD1 / 64, NNODES / 64, 12,
                &g_tick[0], ltid, wg, gsm);
    gridbar();
    // P1: combine -> z1 + layer1 scores (fused)
    ph_combine_scores1(g_part, 12, a1, g_z1, g_ssrc, g_sdst, sm);
    gridbar();
    // P2: layer1 stats
    ph_stats(g_ssrc, g_sdst, g_Af, g_Cf, g_Bp, g_Dp, NHEAD, ltid, wg, grp, ngrp, gsm);
    gridbar();
    // P3: agg1 partials, split 8 (256 jobs)
    ph_gemm_agg(g_z1, g_part, g_ssrc, g_sdst, g_Af, g_Cf, g_Bp, g_Dp,
                HD1, HIDD, 1, NNODES / 64, 8, NHEAD, 64, HD1,
                &g_tick[1], ltid, wg, gsm);
    gridbar();
    // P4: combine + ELU -> h1
    ph_combine(g_h1, g_part, 8, NNODES * HD1, 2);
    gridbar();
    // P5: z2 partials = h1 @ W2^T, split 4 (384 jobs)
    ph_gemm_abt(g_h1, W2, g_part, IND, HD1, 64, IND / 64, NNODES / 64, 4,
                &g_tick[2], ltid, wg, gsm);
    gridbar();
    // P6: combine -> z2 + layer2 scores (fused)
    ph_combine_scores2(g_part, 4, a2, g_z2, g_ssrc, g_sdst, sm);
    gridbar();
    // P7: layer2 stats
    ph_stats(g_ssrc, g_sdst, g_Af, g_Cf, g_Bp, g_Dp, 1, ltid, wg, grp, ngrp, gsm);
    gridbar();
    // P8: agg2 partials, split 4 (384 jobs, klen 128)
    ph_gemm_agg(g_z2, g_part, g_ssrc, g_sdst, g_Af, g_Cf, g_Bp, g_Dp,
                IND, 0, IND / 64, NNODES / 64, 4, 1, 128, IND,
                &g_tick[3], ltid, wg, gsm);
    gridbar();
    // P9: combine -> h2
    ph_combine(g_h2, g_part, 4, NNODES * IND, 0);
    gridbar();
    // P10: column softmax stats (48 jobs)
    ph_colstats(g_h2, g_mxc, g_invc, ltid, wg, grp, ngrp, gsm);
    gridbar();
    // P11: fc1 partials = softmax(h2) @ fc1_w^T (exp fused), 384 jobs
    ph_gemm_fc1(g_h2, g_mxc, g_invc, fc1w, g_part, &g_tick[4], ltid, wg, gsm);
    gridbar();
    // P12: combine + bias + relu -> r, + atomic column sum (fused)
    ph_combine_relu_colsum(g_part, 16, fc1b, g_r, sm);
    gridbar();
    // P13: fc2 -> out
    ph_fc2(g_rsum, fc2w, fc2b, out);
}

// ----------------------------------------------------------------------------
// Launch
// ----------------------------------------------------------------------------
extern "C" void kernel_launch(void* const* d_in, const int* in_sizes, int n_in,
                              void* d_out, int out_size)
{
    const float* X     = (const float*)d_in[0];
    const float* W1    = (const float*)d_in[1];
    const float* a1    = (const float*)d_in[2];
    const float* W2    = (const float*)d_in[3];
    const float* a2    = (const float*)d_in[4];
    const float* fc1_w = (const float*)d_in[5];
    const float* fc1_b = (const float*)d_in[6];
    const float* fc2_w = (const float*)d_in[7];
    const float* fc2_b = (const float*)d_in[8];

    int sms = 148;
    cudaDeviceGetAttribute(&sms, cudaDevAttrMultiProcessorCount, 0);

    const size_t smbytes = (size_t)NG * SMG * sizeof(float);   // ~61 KB
    cudaFuncSetAttribute(gat_mega, cudaFuncAttributeMaxDynamicSharedMemorySize,
                         (int)smbytes);

    gat_mega<<<sms, NT, smbytes>>>(X, W1, a1, W2, a2, fc1_w, fc1_b, fc2_w, fc2_b,
                                   (float*)d_out);
}

// round 16
// speedup vs baseline: 1.1670x; 1.0249x over previous
#include <cuda_runtime.h>
#include <math.h>

#define NNODES 512
#define IND    768
#define HIDD   64
#define NHEAD  4
#define HD1    256
#define KCC    192
#define OUTDIM 256
#define NT     768
#define NG     3
#define GSZ    256
#define SMG    7936         // smem floats per warpgroup (3-stage buffers)
#define RS     20           // smem row stride (16 k + 4 pad)
#define JOBSLOT 7880        // per-group smem job ticket slot

// ----------------------------------------------------------------------------
// Device scratch
// ----------------------------------------------------------------------------
__device__ __align__(16) float g_z1[NNODES * HD1];
__device__ __align__(16) float g_h1[NNODES * HD1];
__device__ __align__(16) float g_z2[NNODES * IND];
__device__ __align__(16) float g_h2[NNODES * IND];
__device__ __align__(16) float g_r [NNODES * KCC];
__device__ __align__(16) float g_part[4 * NNODES * IND];
__device__ __align__(16) float g_ssrc[NHEAD * NNODES];
__device__ __align__(16) float g_sdst[NHEAD * NNODES];
__device__ __align__(16) float g_Af[NHEAD * NNODES];
__device__ __align__(16) float g_Cf[NHEAD * NNODES];
__device__ __align__(16) float g_Bp[NHEAD * NNODES];
__device__ __align__(16) float g_Dp[NHEAD * NNODES];
__device__ __align__(16) float g_mxc[IND], g_invc[IND];
__device__ float g_rsum[KCC];
__device__ unsigned g_tick[8];
__device__ unsigned g_cnt8[8];
__device__ unsigned g_root = 0;
__device__ volatile unsigned g_bargen = 0;

// ----------------------------------------------------------------------------
// Barriers + cp.async helpers
// ----------------------------------------------------------------------------
__device__ __forceinline__ void wgsync(int wg) {
    asm volatile("bar.sync %0, %1;" :: "r"(wg + 1), "n"(GSZ) : "memory");
}

__device__ __forceinline__ void gridbar() {
    __syncthreads();
    if (threadIdx.x == 0) {
        __threadfence();
        const unsigned gen = g_bargen;
        const unsigned b = blockIdx.x & 7u;
        const unsigned bsz = (gridDim.x >> 3) + (((gridDim.x & 7u) > b) ? 1u : 0u);
        if (atomicAdd(&g_cnt8[b], 1u) == bsz - 1u) {
            atomicExch(&g_cnt8[b], 0u);
            __threadfence();
            if (atomicAdd(&g_root, 1u) == 7u) {
                atomicExch(&g_root, 0u);
                __threadfence();
                atomicAdd((unsigned*)&g_bargen, 1u);
            }
        }
        while (g_bargen == gen) { __nanosleep(32); }
        __threadfence();
    }
    __syncthreads();
}

__device__ __forceinline__ unsigned su32(const void* p) {
    return (unsigned)__cvta_generic_to_shared(p);
}
__device__ __forceinline__ void cpa16(unsigned d, const void* s) {
    asm volatile("cp.async.cg.shared.global [%0], [%1], 16;" :: "r"(d), "l"(s));
}
__device__ __forceinline__ void cpcommit() { asm volatile("cp.async.commit_group;"); }
__device__ __forceinline__ void cpwait0()  { asm volatile("cp.async.wait_group 0;"); }
__device__ __forceinline__ void cpwait1()  { asm volatile("cp.async.wait_group 1;"); }

__device__ __forceinline__ int steal(unsigned* tick, int njobs, int ltid, int wg,
                                     float* gsm)
{
    volatile unsigned* slot = (volatile unsigned*)(gsm + JOBSLOT);
    if (ltid == 0) *slot = atomicAdd(tick, 1u);
    wgsync(wg);
    int job = (int)*slot;
    return (job < njobs) ? job : -1;
}

// ----------------------------------------------------------------------------
// TF32 MMA helpers (m16n8k8). 3-pass split precision (~fp32) and 1-pass.
// ----------------------------------------------------------------------------
__device__ __forceinline__ unsigned f2tf(float x) {
    unsigned r; asm("cvt.rna.tf32.f32 %0, %1;" : "=r"(r) : "f"(x)); return r;
}
__device__ __forceinline__ void mma8(float* c, unsigned a0, unsigned a1,
                                     unsigned a2, unsigned a3,
                                     unsigned b0, unsigned b1) {
    asm volatile("mma.sync.aligned.m16n8k8.row.col.f32.tf32.tf32.f32 "
                 "{%0,%1,%2,%3}, {%4,%5,%6,%7}, {%8,%9}, {%0,%1,%2,%3};"
                 : "+f"(c[0]), "+f"(c[1]), "+f"(c[2]), "+f"(c[3])
                 : "r"(a0), "r"(a1), "r"(a2), "r"(a3), "r"(b0), "r"(b1));
}

// 16x32 warp-tile, one k16 chunk. Ab: [m][k] stride RS. Bb: [n][k] stride RS.
__device__ __forceinline__ void mma_chunk_abt(const float* Ab, const float* Bb,
                                              int wm, int wn, int g, int t,
                                              float acc[4][4])
{
#pragma unroll
    for (int s = 0; s < 2; s++) {
        const float* Ar = Ab + (16 * wm) * RS + 8 * s + t;
        float a0f = Ar[g * RS],     a1f = Ar[(g + 8) * RS];
        float a2f = Ar[g * RS + 4], a3f = Ar[(g + 8) * RS + 4];
        unsigned ah0 = f2tf(a0f), ah1 = f2tf(a1f), ah2 = f2tf(a2f), ah3 = f2tf(a3f);
        unsigned al0 = __float_as_uint(a0f - __uint_as_float(ah0));
        unsigned al1 = __float_as_uint(a1f - __uint_as_float(ah1));
        unsigned al2 = __float_as_uint(a2f - __uint_as_float(ah2));
        unsigned al3 = __float_as_uint(a3f - __uint_as_float(ah3));
#pragma unroll
        for (int nf = 0; nf < 4; nf++) {
            const float* Br = Bb + (32 * wn + 8 * nf + g) * RS + 8 * s + t;
            float b0f = Br[0], b1f = Br[4];
            unsigned bh0 = f2tf(b0f), bh1 = f2tf(b1f);
            unsigned bl0 = __float_as_uint(b0f - __uint_as_float(bh0));
            unsigned bl1 = __float_as_uint(b1f - __uint_as_float(bh1));
            mma8(acc[nf], ah0, ah1, ah2, ah3, bh0, bh1);
            mma8(acc[nf], al0, al1, al2, al3, bh0, bh1);
            mma8(acc[nf], ah0, ah1, ah2, ah3, bl0, bl1);
        }
    }
}

// Single-pass variant (fc1 only — output is averaged downstream, TF32 error safe)
__device__ __forceinline__ void mma_chunk_abt_1p(const float* Ab, const float* Bb,
                                                 int wm, int wn, int g, int t,
                                                 float acc[4][4])
{
#pragma unroll
    for (int s = 0; s < 2; s++) {
        const float* Ar = Ab + (16 * wm) * RS + 8 * s + t;
        unsigned ah0 = f2tf(Ar[g * RS]),     ah1 = f2tf(Ar[(g + 8) * RS]);
        unsigned ah2 = f2tf(Ar[g * RS + 4]), ah3 = f2tf(Ar[(g + 8) * RS + 4]);
#pragma unroll
        for (int nf = 0; nf < 4; nf++) {
            const float* Br = Bb + (32 * wn + 8 * nf + g) * RS + 8 * s + t;
            unsigned bh0 = f2tf(Br[0]), bh1 = f2tf(Br[4]);
            mma8(acc[nf], ah0, ah1, ah2, ah3, bh0, bh1);
        }
    }
}

// B in [k][n] layout, stride 68 (agg Z tiles)
__device__ __forceinline__ void mma_chunk_agg(const float* Ab, const float* Zb,
                                              int wm, int wn, int g, int t,
                                              float acc[4][4])
{
#pragma unroll
    for (int s = 0; s < 2; s++) {
        const float* Ar = Ab + (16 * wm) * RS + 8 * s + t;
        float a0f = Ar[g * RS],     a1f = Ar[(g + 8) * RS];
        float a2f = Ar[g * RS + 4], a3f = Ar[(g + 8) * RS + 4];
        unsigned ah0 = f2tf(a0f), ah1 = f2tf(a1f), ah2 = f2tf(a2f), ah3 = f2tf(a3f);
        unsigned al0 = __float_as_uint(a0f - __uint_as_float(ah0));
        unsigned al1 = __float_as_uint(a1f - __uint_as_float(ah1));
        unsigned al2 = __float_as_uint(a2f - __uint_as_float(ah2));
        unsigned al3 = __float_as_uint(a3f - __uint_as_float(ah3));
#pragma unroll
        for (int nf = 0; nf < 4; nf++) {
            const float* Br = Zb + (8 * s + t) * 68 + 32 * wn + 8 * nf + g;
            float b0f = Br[0], b1f = Br[4 * 68];
            unsigned bh0 = f2tf(b0f), bh1 = f2tf(b1f);
            unsigned bl0 = __float_as_uint(b0f - __uint_as_float(bh0));
            unsigned bl1 = __float_as_uint(b1f - __uint_as_float(bh1));
            mma8(acc[nf], ah0, ah1, ah2, ah3, bh0, bh1);
            mma8(acc[nf], al0, al1, al2, al3, bh0, bh1);
            mma8(acc[nf], ah0, ah1, ah2, ah3, bl0, bl1);
        }
    }
}

__device__ __forceinline__ void store_tile(float* outp, int ld, int m0, int n0,
                                           int wm, int wn, int g, int t,
                                           float acc[4][4])
{
    const int r0 = m0 + 16 * wm + g;
    const int cb = n0 + 32 * wn + 2 * t;
#pragma unroll
    for (int nf = 0; nf < 4; nf++) {
        *(float2*)&outp[(size_t)r0 * ld + cb + 8 * nf] =
            make_float2(acc[nf][0], acc[nf][1]);
        *(float2*)&outp[(size_t)(r0 + 8) * ld + cb + 8 * nf] =
            make_float2(acc[nf][2], acc[nf][3]);
    }
}

// ----------------------------------------------------------------------------
// SGEMM 64x64 via TF32 MMA, 3-stage cp.async pipeline, stealing.
// smem: As[3][1280] @0, Bs[3][1280] @3840.
// ----------------------------------------------------------------------------
__device__ void ph_gemm_abt(const float* __restrict__ A, const float* __restrict__ B,
                            float* __restrict__ C, int Ncols, int K_ld, int klen,
                            int gx, int gy, int nsplit, unsigned* tick,
                            int ltid, int wg, float* gsm)
{
    float* As = gsm;
    float* Bs = gsm + 3840;
    const int w = ltid >> 5, wm = w >> 1, wn = w & 1;
    const int lane = ltid & 31, g = lane >> 2, t = lane & 3;
    const int isB  = ltid >> 7;
    const int lrow = (ltid & 127) >> 1;
    const int lh   = ltid & 1;
    const int njobs = gx * gy * nsplit;
    const int nch = klen >> 4;

    for (;;) {
        const int job = steal(tick, njobs, ltid, wg, gsm);   // wgsync inside
        if (job < 0) break;
        const int z = job / (gx * gy);
        const int rem = job % (gx * gy);
        const int by = rem / gx, bx = rem % gx;
        const int m0 = by * 64, n0 = bx * 64, kstart = z * klen;

        const float* src0 = isB ? (B + (size_t)(n0 + lrow) * K_ld + kstart + lh * 8)
                                : (A + (size_t)(m0 + lrow) * K_ld + kstart + lh * 8);
        const unsigned dst0 = isB ? su32(&Bs[lrow * RS + lh * 8])
                                  : su32(&As[lrow * RS + lh * 8]);

        auto stage = [&](int cc) {
            const unsigned off = (unsigned)(cc % 3) * 5120u;
            const float* s = src0 + cc * 16;
            cpa16(dst0 + off, s);
            cpa16(dst0 + off + 16, s + 4);
            cpcommit();
        };

        float acc[4][4];
#pragma unroll
        for (int i = 0; i < 4; i++)
#pragma unroll
            for (int j = 0; j < 4; j++) acc[i][j] = 0.f;

        stage(0);
        if (nch > 1) stage(1);

        for (int c = 0; c < nch; c++) {
            if (c + 1 < nch) cpwait1(); else cpwait0();
            wgsync(wg);                       // buf (c+2)%3 free; data c visible
            if (c + 2 < nch) stage(c + 2);
            const int cb = c % 3;
            mma_chunk_abt(As + cb * 1280, Bs + cb * 1280, wm, wn, g, t, acc);
        }
        wgsync(wg);     // done with smem before next steal overwrites

        store_tile(C + (size_t)z * NNODES * Ncols, Ncols, m0, n0, wm, wn, g, t, acc);
    }
}

// ----------------------------------------------------------------------------
// Aggregation GEMM 64x64 via TF32 MMA, 3-stage pipeline; alpha built on the fly.
// smem: Ab[3][1280] @0 ([j][k] stride RS), Zs[3][1088] @3840, Ex[192] @7104.
// ----------------------------------------------------------------------------
__device__ void ph_gemm_agg(const float* __restrict__ Z, float* __restrict__ C,
                            const float* __restrict__ ssrc, const float* __restrict__ sdst,
                            const float* __restrict__ Af, const float* __restrict__ Cf,
                            const float* __restrict__ Bp, const float* __restrict__ Dp,
                            int ldz, int hd, int gx, int gy, int nsplit, int H,
                            int klen, int ldc, unsigned* tick,
                            int ltid, int wg, float* gsm)
{
    float* Ab3 = gsm;
    float* Zs  = gsm + 3840;
    float* Ex  = gsm + 7104;
    const int w = ltid >> 5, wm = w >> 1, wn = w & 1;
    const int lane = ltid & 31, g = lane >> 2, t = lane & 3;
    const int zrow = ltid >> 4, zf4 = ltid & 15;
    const int jrow = ltid >> 2, i4 = (ltid & 3) * 4;
    const int jobs_per_h = gx * gy * nsplit;
    const int njobs = H * jobs_per_h;
    const int nch = klen >> 4;

    for (;;) {
        const int job = steal(tick, njobs, ltid, wg, gsm);
        if (job < 0) break;
        const int h = job / jobs_per_h;
        int rem = job % jobs_per_h;
        const int z = rem / (gx * gy); rem %= gx * gy;
        const int by = rem / gx, bx = rem % gx;
        const int m0 = by * 64, ncol0 = h * hd + bx * 64, kstart = z * klen;
        const float* ss = ssrc + h * NNODES;
        const float* af = Af + h * NNODES;
        const float* cf = Cf + h * NNODES;

        auto build = [&](int cc) {
            float* dst = Ab3 + (cc % 3) * 1280;
            const int base = kstart + cc * 16 + i4;
            float4 s4 = *(const float4*)&ss[base];
            float4 a4 = *(const float4*)&af[base];
            float4 c4 = *(const float4*)&cf[base];
            const float dj  = Ex[jrow];
            const float bpj = Ex[64 + jrow];
            const float dpj = Ex[128 + jrow];
            const int jg = m0 + jrow;
            float4 wv;
            wv.x = (s4.x + dj > 0.f) ? a4.x * bpj : c4.x * dpj;
            wv.y = (s4.y + dj > 0.f) ? a4.y * bpj : c4.y * dpj;
            wv.z = (s4.z + dj > 0.f) ? a4.z * bpj : c4.z * dpj;
            wv.w = (s4.w + dj > 0.f) ? a4.w * bpj : c4.w * dpj;
            if (base + 0 == jg) wv.x = 0.f;
            if (base + 1 == jg) wv.y = 0.f;
            if (base + 2 == jg) wv.z = 0.f;
            if (base + 3 == jg) wv.w = 0.f;
            *(float4*)&dst[jrow * RS + i4] = wv;
        };

        const float* srcZ = Z + (size_t)(kstart + zrow) * ldz + ncol0 + zf4 * 4;
        const unsigned dstZ = su32(&Zs[zrow * 68 + zf4 * 4]);
        auto stageZ = [&](int cc) {
            cpa16(dstZ + (unsigned)(cc % 3) * 4352u, srcZ + (size_t)cc * 16 * ldz);
            cpcommit();
        };

        if (ltid < 64) {
            int j = m0 + ltid;
            Ex[ltid]       = sdst[h * NNODES + j];
            Ex[64 + ltid]  = Bp[h * NNODES + j];
            Ex[128 + ltid] = Dp[h * NNODES + j];
        }
        wgsync(wg);                         // Ex visible to ALL threads

        build(0);
        stageZ(0);
        if (nch > 1) { build(1); stageZ(1); }

        float acc[4][4];
#pragma unroll
        for (int i = 0; i < 4; i++)
#pragma unroll
            for (int j = 0; j < 4; j++) acc[i][j] = 0.f;

        for (int c = 0; c < nch; c++) {
            if (c + 1 < nch) cpwait1(); else cpwait0();
            wgsync(wg);
            if (c + 2 < nch) { stageZ(c + 2); build(c + 2); }
            const int cb = c % 3;
            mma_chunk_agg(Ab3 + cb * 1280, Zs + cb * 1088, wm, wn, g, t, acc);
        }
        wgsync(wg);

        store_tile(C + (size_t)z * NNODES * ldc, ldc, m0, ncol0, wm, wn, g, t, acc);
    }
}

// ----------------------------------------------------------------------------
// fc1 GEMM: single-pass TF32, 3-stage pipeline, softmax folded into A build.
// smem: As[3][1280] @0, Bs[3][1280] @3840.
// ----------------------------------------------------------------------------
__device__ void ph_gemm_fc1(const float* __restrict__ h2m, const float* __restrict__ mxc,
                            const float* __restrict__ invc, const float* __restrict__ Bw,
                            float* __restrict__ C, unsigned* tick,
                            int ltid, int wg, float* gsm)
{
    float* As = gsm;
    float* Bs = gsm + 3840;
    const int w = ltid >> 5, wm = w >> 1, wn = w & 1;
    const int lane = ltid & 31, g = lane >> 2, t = lane & 3;
    const int row = ltid >> 2, kq = (ltid & 3) * 4;
    const int njobs = 384;
    const int nch = 3;

    for (;;) {
        const int job = steal(tick, njobs, ltid, wg, gsm);
        if (job < 0) break;
        const int z = job / 24;
        const int rem = job % 24;
        const int by = rem / 3, bx = rem % 3;
        const int m0 = by * 64, n0 = bx * 64, kstart = z * 48;

        const unsigned dstB = su32(&Bs[row * RS + kq]);
        const float* srcB = Bw + (size_t)(n0 + row) * IND + kstart + kq;
        const float* srcA = h2m + (size_t)(m0 + row) * IND + kstart + kq;

        auto stageB = [&](int cc) {
            cpa16(dstB + (unsigned)(cc % 3) * 5120u, srcB + cc * 16);
            cpcommit();
        };
        auto buildA = [&](int cc) {
            const int kg = kstart + cc * 16 + kq;
            float4 raw = *(const float4*)(srcA + cc * 16);
            float4 mx  = *(const float4*)&mxc[kg];
            float4 iv  = *(const float4*)&invc[kg];
            float4 v;
            v.x = __expf(raw.x - mx.x) * iv.x;
            v.y = __expf(raw.y - mx.y) * iv.y;
            v.z = __expf(raw.z - mx.z) * iv.z;
            v.w = __expf(raw.w - mx.w) * iv.w;
            *(float4*)&As[(cc % 3) * 1280 + row * RS + kq] = v;
        };

        float acc[4][4];
#pragma unroll
        for (int i = 0; i < 4; i++)
#pragma unroll
            for (int j = 0; j < 4; j++) acc[i][j] = 0.f;

        buildA(0); stageB(0);
        buildA(1); stageB(1);

        for (int c = 0; c < nch; c++) {
            if (c + 1 < nch) cpwait1(); else cpwait0();
            wgsync(wg);
            if (c + 2 < nch) { stageB(c + 2); buildA(c + 2); }
            const int cb = c % 3;
            mma_chunk_abt_1p(As + cb * 1280, Bs + cb * 1280, wm, wn, g, t, acc);
        }
        wgsync(wg);

        store_tile(C + (size_t)z * NNODES * KCC, KCC, m0, n0, wm, wn, g, t, acc);
    }
}

// ----------------------------------------------------------------------------
// Fused combine + layer1 scores. Block (768 thr) = 3 rows of z1 per iteration.
// ----------------------------------------------------------------------------
__device__ void ph_combine_scores1(const float* __restrict__ part, int nparts,
                                   const float* __restrict__ a1,
                                   float* __restrict__ z1,
                                   float* __restrict__ ssrc, float* __restrict__ sdst,
                                   float* smblk)
{
    const int tid = threadIdx.x;
    const int total = NNODES * HD1;
    const int d = tid & 255, h = d >> 6, l = d & 63;
    const float a_s = a1[h * 128 + l];
    const float a_d = a1[h * 128 + 64 + l];

    for (int base = blockIdx.x * NT; base < total; base += gridDim.x * NT) {
        const int idx = base + tid;
        float v = 0.f;
        if (idx < total) {
            for (int p = 0; p < nparts; p++) v += part[(size_t)p * total + idx];
            z1[idx] = v;
        }
        float s1 = v * a_s, s2 = v * a_d;
#pragma unroll
        for (int o = 16; o; o >>= 1) {
            s1 += __shfl_xor_sync(0xffffffffu, s1, o);
            s2 += __shfl_xor_sync(0xffffffffu, s2, o);
        }
        const int wq = tid >> 5;
        if ((tid & 31) == 0) { smblk[wq] = s1; smblk[24 + wq] = s2; }
        __syncthreads();
        if (tid < 12) {
            float t1 = smblk[2 * tid] + smblk[2 * tid + 1];
            float t2 = smblk[24 + 2 * tid] + smblk[24 + 2 * tid + 1];
            int row = (base >> 8) + (tid >> 2);
            int hh = tid & 3;
            if (row < NNODES) {
                ssrc[hh * NNODES + row] = t1;
                sdst[hh * NNODES + row] = t2;
            }
        }
        __syncthreads();
    }
}

// ----------------------------------------------------------------------------
// Fused combine + layer2 scores. Block = exactly 1 row of z2 per iteration.
// ----------------------------------------------------------------------------
__device__ void ph_combine_scores2(const float* __restrict__ part, int nparts,
                                   const float* __restrict__ a2,
                                   float* __restrict__ z2,
                                   float* __restrict__ ssrc, float* __restrict__ sdst,
                                   float* smblk)
{
    const int tid = threadIdx.x;
    const int total = NNODES * IND;
    const float a_s = a2[tid];
    const float a_d = a2[IND + tid];

    for (int base = blockIdx.x * NT; base < total; base += gridDim.x * NT) {
        const int idx = base + tid;
        float v = 0.f;
        for (int p = 0; p < nparts; p++) v += part[(size_t)p * total + idx];
        z2[idx] = v;
        float s1 = v * a_s, s2 = v * a_d;
#pragma unroll
        for (int o = 16; o; o >>= 1) {
            s1 += __shfl_xor_sync(0xffffffffu, s1, o);
            s2 += __shfl_xor_sync(0xffffffffu, s2, o);
        }
        const int wq = tid >> 5;
        if ((tid & 31) == 0) { smblk[wq] = s1; smblk[24 + wq] = s2; }
        __syncthreads();
        if (tid == 0) {
            float t1 = 0.f, t2 = 0.f;
            for (int q = 0; q < 24; q++) { t1 += smblk[q]; t2 += smblk[24 + q]; }
            const int row = base / IND;
            ssrc[row] = t1;
            sdst[row] = t2;
        }
        __syncthreads();
    }
}

// ----------------------------------------------------------------------------
// Fused fc1 combine + bias + relu + column-sum (atomic). Block = 4 rows of r.
// ----------------------------------------------------------------------------
__device__ void ph_combine_relu_colsum(const float* __restrict__ part, int nparts,
                                       const float* __restrict__ bias,
                                       float* __restrict__ r, float* smblk)
{
    const int tid = threadIdx.x;
    const int total = NNODES * KCC;
    const float b = bias[tid % KCC];

    for (int base = blockIdx.x * NT; base < total; base += gridDim.x * NT) {
        const int idx = base + tid;
        float v = 0.f;
        for (int p = 0; p < nparts; p++) v += part[(size_t)p * total + idx];
        v = fmaxf(v + b, 0.f);
        r[idx] = v;
        smblk[tid] = v;
        __syncthreads();
        if (tid < KCC)
            atomicAdd(&g_rsum[tid],
                      smblk[tid] + smblk[tid + KCC] + smblk[tid + 2 * KCC] +
                      smblk[tid + 3 * KCC]);
        __syncthreads();
    }
}

// ----------------------------------------------------------------------------
// Plain combine (ELU / none), vectorized float4
// ----------------------------------------------------------------------------
__device__ void ph_combine(float* __restrict__ out, const float* __restrict__ part,
                           int nparts, int total, int act)
{
    const int total4 = total / 4;
    const float4* part4 = (const float4*)part;
    for (int q = blockIdx.x * NT + threadIdx.x; q < total4; q += gridDim.x * NT) {
        float4 s = make_float4(0.f, 0.f, 0.f, 0.f);
        for (int p = 0; p < nparts; p++) {
            float4 v = part4[(size_t)p * total4 + q];
            s.x += v.x; s.y += v.y; s.z += v.z; s.w += v.w;
        }
        if (act == 2) {
            s.x = s.x > 0.f ? s.x : expm1f(s.x);
            s.y = s.y > 0.f ? s.y : expm1f(s.y);
            s.z = s.z > 0.f ? s.z : expm1f(s.z);
            s.w = s.w > 0.f ? s.w : expm1f(s.w);
        }
        *(float4*)&out[q * 4] = s;
    }
}

// ----------------------------------------------------------------------------
// Separable-softmax stats (static mapping; 32 / 8 jobs)
// ----------------------------------------------------------------------------
__device__ void ph_stats(const float* __restrict__ ssrc, const float* __restrict__ sdst,
                         float* __restrict__ Af, float* __restrict__ Cf,
                         float* __restrict__ Bpg, float* __restrict__ Dpg,
                         int H, int ltid, int wg, int grp, int ngrp, float* gsm)
{
    float* ss  = gsm;
    float* aa  = gsm + 512;
    float* cc  = gsm + 1024;
    float* rm1 = gsm + 1536;
    float* rm2 = gsm + 1792;
    int*   ri1 = (int*)(gsm + 2048);
    const int cpj = NNODES / 64;
    const int njobs = H * cpj;

    for (int job = grp; job < njobs; job += ngrp) {
        const int h = job / cpj, jc = job % cpj;
        wgsync(wg);
        for (int i = ltid; i < NNODES; i += GSZ) ss[i] = ssrc[h * NNODES + i];
        wgsync(wg);

        float m1 = -1e30f, m2 = -1e30f; int i1 = -1;
        for (int i = ltid; i < NNODES; i += GSZ) {
            float v = ss[i];
            if (v > m1) { m2 = m1; m1 = v; i1 = i; }
            else if (v > m2) m2 = v;
        }
        rm1[ltid] = m1; rm2[ltid] = m2; ri1[ltid] = i1;
        wgsync(wg);
        if (ltid < 32) {
            float a1 = rm1[ltid], a2 = rm2[ltid]; int ai = ri1[ltid];
            for (int tt = ltid + 32; tt < GSZ; tt += 32) {
                float b1 = rm1[tt], b2 = rm2[tt];
                if (b1 > a1) { a2 = fmaxf(a1, b2); a1 = b1; ai = ri1[tt]; }
                else         { a2 = fmaxf(a2, b1); }
            }
            rm1[ltid] = a1; rm2[ltid] = a2; ri1[ltid] = ai;
        }
        wgsync(wg);
        if (ltid == 0) {
            float a1 = rm1[0], a2 = rm2[0]; int ai = ri1[0];
            for (int tt = 1; tt < 32; tt++) {
                float b1 = rm1[tt], b2 = rm2[tt];
                if (b1 > a1) { a2 = fmaxf(a1, b2); a1 = b1; ai = ri1[tt]; }
                else         { a2 = fmaxf(a2, b1); }
            }
            rm1[0] = a1; rm2[0] = a2; ri1[0] = ai;
        }
        wgsync(wg);
        const float Ms = rm1[0], M2 = rm2[0];
        const int iarg = ri1[0];

        for (int i = ltid; i < NNODES; i += GSZ) {
            float dd = ss[i] - Ms;
            aa[i] = __expf(dd);
            cc[i] = __expf(0.01f * dd);
        }
        wgsync(wg);
        if (jc == 0) {
            for (int i = ltid; i < NNODES; i += GSZ) {
                Af[h * NNODES + i] = aa[i];
                Cf[h * NNODES + i] = cc[i];
            }
        }

        const int wid = ltid >> 5, lane = ltid & 31;
        for (int jj = wid; jj < 64; jj += 8) {
            int j = jc * 64 + jj;
            float sd = sdst[h * NNODES + j];
            float smx = (j == iarg) ? M2 : Ms;
            float t0 = smx + sd;
            float mxj = t0 > 0.f ? t0 : 0.01f * t0;
            float Bj = __expf(Ms + sd - mxj);
            float Dj = __expf(0.01f * (Ms + sd) - mxj);
            float ssum = 0.f;
            for (int i = lane; i < NNODES; i += 32) {
                if (i == j) continue;
                float x = ss[i] + sd;
                ssum += (x > 0.f) ? aa[i] * Bj : cc[i] * Dj;
            }
#pragma unroll
            for (int o = 16; o; o >>= 1) ssum += __shfl_xor_sync(0xffffffffu, ssum, o);
            if (lane == 0) {
                float inv = 1.f / ssum;
                Bpg[h * NNODES + j] = Bj * inv;
                Dpg[h * NNODES + j] = Dj * inv;
            }
        }
    }
}

// ----------------------------------------------------------------------------
// Column softmax stats: 48 jobs x 16 features; 16 thr/col.
// ----------------------------------------------------------------------------
__device__ void ph_colstats(const float* __restrict__ h2,
                            float* __restrict__ mxc, float* __restrict__ invc,
                            int ltid, int wg, int grp, int ngrp, float* gsm)
{
    float* red  = gsm;
    float* red2 = gsm + 256;
    const int fl = ltid & 15, rg = ltid >> 4;
    for (int job = grp; job < IND / 16; job += ngrp) {
        const int f = job * 16 + fl;
        wgsync(wg);
        float m = -1e30f;
        for (int r0 = rg; r0 < NNODES; r0 += 16) m = fmaxf(m, h2[(size_t)r0 * IND + f]);
        red[rg * 16 + fl] = m;
        wgsync(wg);
        if (rg == 0) {
            float mm = red[fl];
#pragma unroll
            for (int gq = 1; gq < 16; gq++) mm = fmaxf(mm, red[gq * 16 + fl]);
            red[fl] = mm;
        }
        wgsync(wg);
        const float mf = red[fl];
        float s = 0.f;
        for (int r0 = rg; r0 < NNODES; r0 += 16) s += __expf(h2[(size_t)r0 * IND + f] - mf);
        red2[rg * 16 + fl] = s;
        wgsync(wg);
        if (rg == 0) {
            float tq = 0.f;
#pragma unroll
            for (int gq = 0; gq < 16; gq++) tq += red2[gq * 16 + fl];
            mxc[f] = mf;
            invc[f] = 1.f / tq;
        }
    }
}

// ----------------------------------------------------------------------------
// fc2: warp per output
// ----------------------------------------------------------------------------
__device__ void ph_fc2(const float* __restrict__ rsum, const float* __restrict__ w,
                       const float* __restrict__ b, float* __restrict__ out)
{
    const int lane = threadIdx.x & 31;
    const int gw = blockIdx.x * (NT / 32) + (threadIdx.x >> 5);
    const int nw = gridDim.x * (NT / 32);
    for (int o = gw; o < OUTDIM; o += nw) {
        float s = 0.f;
        for (int k = lane; k < KCC; k += 32) s += rsum[k] * w[(size_t)o * KCC + k];
#pragma unroll
        for (int of = 16; of; of >>= 1) s += __shfl_xor_sync(0xffffffffu, s, of);
        if (lane == 0) out[o] = (float)NNODES * b[o] + s;
    }
}

// ----------------------------------------------------------------------------
// Persistent mega-kernel
// ----------------------------------------------------------------------------
__global__ void __launch_bounds__(NT, 1)
gat_mega(const float* __restrict__ X,  const float* __restrict__ W1,
         const float* __restrict__ a1, const float* __restrict__ W2,
         const float* __restrict__ a2, const float* __restrict__ fc1w,
         const float* __restrict__ fc1b, const float* __restrict__ fc2w,
         const float* __restrict__ fc2b, float* __restrict__ out)
{
    extern __shared__ float sm[];
    const int wg = threadIdx.x >> 8;
    const int ltid = threadIdx.x & 255;
    float* gsm = sm + wg * SMG;
    const int grp = wg * gridDim.x + blockIdx.x;
    const int ngrp = gridDim.x * NG;

    // INIT: reset tickets + rsum
    if (blockIdx.x == 0) {
        if (threadIdx.x < 8) g_tick[threadIdx.x] = 0;
        if (threadIdx.x >= 32 && threadIdx.x < 32 + KCC) g_rsum[threadIdx.x - 32] = 0.f;
    }
    gridbar();
    // P0: z1 partials = X @ W1^T, split 12 (384 jobs)
    ph_gemm_abt(X, W1, g_part, HD1, IND, 64, HD1 / 64, NNODES / 64, 12,
                &g_tick[0], ltid, wg, gsm);
    gridbar();
    // P1: combine -> z1 + layer1 scores (fused)
    ph_combine_scores1(g_part, 12, a1, g_z1, g_ssrc, g_sdst, sm);
    gridbar();
    // P2: layer1 stats
    ph_stats(g_ssrc, g_sdst, g_Af, g_Cf, g_Bp, g_Dp, NHEAD, ltid, wg, grp, ngrp, gsm);
    gridbar();
    // P3: agg1 partials, split 8 (256 jobs)
    ph_gemm_agg(g_z1, g_part, g_ssrc, g_sdst, g_Af, g_Cf, g_Bp, g_Dp,
                HD1, HIDD, 1, NNODES / 64, 8, NHEAD, 64, HD1,
                &g_tick[1], ltid, wg, gsm);
    gridbar();
    // P4: combine + ELU -> h1
    ph_combine(g_h1, g_part, 8, NNODES * HD1, 2);
    gridbar();
    // P5: z2 partials = h1 @ W2^T, split 4 (384 jobs)
    ph_gemm_abt(g_h1, W2, g_part, IND, HD1, 64, IND / 64, NNODES / 64, 4,
                &g_tick[2], ltid, wg, gsm);
    gridbar();
    // P6: combine -> z2 + layer2 scores (fused)
    ph_combine_scores2(g_part, 4, a2, g_z2, g_ssrc, g_sdst, sm);
    gridbar();
    // P7: layer2 stats
    ph_stats(g_ssrc, g_sdst, g_Af, g_Cf, g_Bp, g_Dp, 1, ltid, wg, grp, ngrp, gsm);
    gridbar();
    // P8: agg2 partials, split 4 (384 jobs, klen 128)
    ph_gemm_agg(g_z2, g_part, g_ssrc, g_sdst, g_Af, g_Cf, g_Bp, g_Dp,
                IND, 0, IND / 64, NNODES / 64, 4, 1, 128, IND,
                &g_tick[3], ltid, wg, gsm);
    gridbar();
    // P9: combine -> h2
    ph_combine(g_h2, g_part, 4, NNODES * IND, 0);
    gridbar();
    // P10: column softmax stats (48 jobs)
    ph_colstats(g_h2, g_mxc, g_invc, ltid, wg, grp, ngrp, gsm);
    gridbar();
    // P11: fc1 partials (single-pass TF32; exp fused), 384 jobs
    ph_gemm_fc1(g_h2, g_mxc, g_invc, fc1w, g_part, &g_tick[4], ltid, wg, gsm);
    gridbar();
    // P12: combine + bias + relu -> r, + atomic column sum (fused)
    ph_combine_relu_colsum(g_part, 16, fc1b, g_r, sm);
    gridbar();
    // P13: fc2 -> out
    ph_fc2(g_rsum, fc2w, fc2b, out);
}

// ----------------------------------------------------------------------------
// Launch
// ----------------------------------------------------------------------------
extern "C" void kernel_launch(void* const* d_in, const int* in_sizes, int n_in,
                              void* d_out, int out_size)
{
    const float* X     = (const float*)d_in[0];
    const float* W1    = (const float*)d_in[1];
    const float* a1    = (const float*)d_in[2];
    const float* W2    = (const float*)d_in[3];
    const float* a2    = (const float*)d_in[4];
    const float* fc1_w = (const float*)d_in[5];
    const float* fc1_b = (const float*)d_in[6];
    const float* fc2_w = (const float*)d_in[7];
    const float* fc2_b = (const float*)d_in[8];

    int sms = 148;
    cudaDeviceGetAttribute(&sms, cudaDevAttrMultiProcessorCount, 0);

    const size_t smbytes = (size_t)NG * SMG * sizeof(float);   // ~93 KB
    cudaFuncSetAttribute(gat_mega, cudaFuncAttributeMaxDynamicSharedMemorySize,
                         (int)smbytes);

    gat_mega<<<sms, NT, smbytes>>>(X, W1, a1, W2, a2, fc1_w, fc1_b, fc2_w, fc2_b,
                                   (float*)d_out);
}